// round 4
// baseline (speedup 1.0000x reference)
#include <cuda_runtime.h>
#include <cuda_bf16.h>
#include <math.h>

#define B_    4
#define T_    4
#define E_    512
#define NH_   8
#define HC_   64
#define HWP_  784
#define NN_   3136
#define ROWS_ 12544
#define SCALE_ 0.125f

__device__ float g_qkv[ROWS_ * 3 * E_];   // pre-scaled q, all tf32-rounded
__device__ float g_sp [ROWS_ * E_];
__device__ float g_qt [ROWS_ * E_];       // tf32-rounded, pre-scaled
__device__ float g_ot [ROWS_ * E_];

__device__ __forceinline__ unsigned f2t(float x) {
    unsigned r; asm("cvt.rna.tf32.f32 %0, %1;" : "=r"(r) : "f"(x)); return r;
}
__device__ __forceinline__ void mma8(float4& d, const unsigned* a, unsigned b0, unsigned b1) {
    asm volatile("mma.sync.aligned.m16n8k8.row.col.f32.tf32.tf32.f32 "
        "{%0,%1,%2,%3},{%4,%5,%6,%7},{%8,%9},{%0,%1,%2,%3};"
        : "+f"(d.x), "+f"(d.y), "+f"(d.z), "+f"(d.w)
        : "r"(a[0]), "r"(a[1]), "r"(a[2]), "r"(a[3]), "r"(b0), "r"(b1));
}
__device__ __forceinline__ void cpa16(void* sdst, const void* gsrc) {
    unsigned s = (unsigned)__cvta_generic_to_shared(sdst);
    asm volatile("cp.async.ca.shared.global [%0], [%1], 16;" :: "r"(s), "l"(gsrc));
}

// ---------------------------------------------------------------------------
// tf32 GEMM, software-pipelined global loads. C[M,N] = A@W^T + bias. Modes:
//  0: plain   1: *scl + tf32-round   2: C += alpha[n]*v (final)
//  3: qkv epilogue: cols<512 scaled by SCALE_, all tf32-rounded
// ---------------------------------------------------------------------------
#define GP 132

__global__ __launch_bounds__(256)
void gemm_tf32(const float* __restrict__ A, const float* __restrict__ W,
               const float* __restrict__ bias, float* __restrict__ C,
               const float* __restrict__ alpha,
               int M, int N, int K, int mode, float scl)
{
    __shared__ unsigned As[16 * GP];
    __shared__ unsigned Bs[16 * GP];
    const int bm = blockIdx.y * 128, bn = blockIdx.x * 128;
    const int tid  = threadIdx.x;
    const int warp = tid >> 5, lane = tid & 31;
    const int wm = (warp >> 1) * 32, wn = (warp & 1) * 64;
    const int row = lane >> 2, t4 = lane & 3;

    const int lr  = tid >> 2;          // 0..63
    const int lc4 = (tid & 3) * 4;
    const float* aP = A + (size_t)(bm + lr) * K + lc4;
    const float* wP = W + (size_t)(bn + lr) * K + lc4;
    const size_t rowK64 = (size_t)64 * K;

    float4 acc[2][8];
#pragma unroll
    for (int i = 0; i < 2; i++)
#pragma unroll
        for (int j = 0; j < 8; j++) acc[i][j] = make_float4(0.f, 0.f, 0.f, 0.f);

    float4 ra0 = *(const float4*)(aP);
    float4 ra1 = *(const float4*)(aP + rowK64);
    float4 rb0 = *(const float4*)(wP);
    float4 rb1 = *(const float4*)(wP + rowK64);

    for (int k0 = 0; k0 < K; k0 += 16) {
        As[(lc4 + 0) * GP + lr] = f2t(ra0.x); As[(lc4 + 1) * GP + lr] = f2t(ra0.y);
        As[(lc4 + 2) * GP + lr] = f2t(ra0.z); As[(lc4 + 3) * GP + lr] = f2t(ra0.w);
        As[(lc4 + 0) * GP + lr + 64] = f2t(ra1.x); As[(lc4 + 1) * GP + lr + 64] = f2t(ra1.y);
        As[(lc4 + 2) * GP + lr + 64] = f2t(ra1.z); As[(lc4 + 3) * GP + lr + 64] = f2t(ra1.w);
        Bs[(lc4 + 0) * GP + lr] = f2t(rb0.x); Bs[(lc4 + 1) * GP + lr] = f2t(rb0.y);
        Bs[(lc4 + 2) * GP + lr] = f2t(rb0.z); Bs[(lc4 + 3) * GP + lr] = f2t(rb0.w);
        Bs[(lc4 + 0) * GP + lr + 64] = f2t(rb1.x); Bs[(lc4 + 1) * GP + lr + 64] = f2t(rb1.y);
        Bs[(lc4 + 2) * GP + lr + 64] = f2t(rb1.z); Bs[(lc4 + 3) * GP + lr + 64] = f2t(rb1.w);
        __syncthreads();

        if (k0 + 16 < K) {   // prefetch next slab; overlaps the mma below
            ra0 = *(const float4*)(aP + k0 + 16);
            ra1 = *(const float4*)(aP + rowK64 + k0 + 16);
            rb0 = *(const float4*)(wP + k0 + 16);
            rb1 = *(const float4*)(wP + rowK64 + k0 + 16);
        }

#pragma unroll
        for (int ks = 0; ks < 16; ks += 8) {
            unsigned a[2][4];
#pragma unroll
            for (int mt = 0; mt < 2; mt++) {
                int rm = wm + mt * 16 + row;
                a[mt][0] = As[(ks + t4) * GP + rm];
                a[mt][1] = As[(ks + t4) * GP + rm + 8];
                a[mt][2] = As[(ks + t4 + 4) * GP + rm];
                a[mt][3] = As[(ks + t4 + 4) * GP + rm + 8];
            }
#pragma unroll
            for (int nt = 0; nt < 8; nt++) {
                int cn = wn + nt * 8 + row;
                unsigned b0 = Bs[(ks + t4) * GP + cn];
                unsigned b1 = Bs[(ks + t4 + 4) * GP + cn];
                mma8(acc[0][nt], a[0], b0, b1);
                mma8(acc[1][nt], a[1], b0, b1);
            }
        }
        __syncthreads();
    }

#pragma unroll
    for (int mt = 0; mt < 2; mt++) {
        int r0g = bm + wm + mt * 16 + row;
#pragma unroll
        for (int nt = 0; nt < 8; nt++) {
            int cg = bn + wn + nt * 8 + 2 * t4;
            float b0 = bias[cg], b1 = bias[cg + 1];
            float v0 = acc[mt][nt].x + b0, v1 = acc[mt][nt].y + b1;
            float v2 = acc[mt][nt].z + b0, v3 = acc[mt][nt].w + b1;
            if (mode == 1) { v0 *= scl; v1 *= scl; v2 *= scl; v3 *= scl; }
            if (mode == 3 && cg < E_) { v0 *= SCALE_; v1 *= SCALE_; v2 *= SCALE_; v3 *= SCALE_; }
            if (mode == 1 || mode == 3) {
                v0 = __uint_as_float(f2t(v0)); v1 = __uint_as_float(f2t(v1));
                v2 = __uint_as_float(f2t(v2)); v3 = __uint_as_float(f2t(v3));
            }
            size_t i0 = (size_t)r0g * N + cg;
            size_t i1 = (size_t)(r0g + 8) * N + cg;
            if (mode == 2) {
                float a0 = alpha[cg], a1 = alpha[cg + 1];
                float2 o0 = *(const float2*)(C + i0);
                float2 o1 = *(const float2*)(C + i1);
                v0 = o0.x + a0 * v0; v1 = o0.y + a1 * v1;
                v2 = o1.x + a0 * v2; v3 = o1.y + a1 * v3;
            }
            *(float2*)(C + i0) = make_float2(v0, v1);
            *(float2*)(C + i1) = make_float2(v2, v3);
        }
    }
}

// ---------------------------------------------------------------------------
// Flash attention, tf32 mma, cp.async double-buffered K/V. 128 thr = 4 warps,
// BQ=64 (16 rows/warp), key tiles of 64, D=64. Inputs already tf32-rounded
// (and q pre-scaled), so staging is a raw 16B copy.
// smem: Qs/Ps[64][68] | Kb[2][64][68] | Vb[2][64][68]
// ---------------------------------------------------------------------------
#define FP 68
#define TILEW (64 * FP)
#define FSMEM (5 * TILEW * 4)

template<int TMP>
__global__ __launch_bounds__(128)
void flash_tf32(const float* __restrict__ qkv, const float* __restrict__ qsrc,
                float* __restrict__ out, int fs, int vs, int accum)
{
    extern __shared__ unsigned sm[];
    unsigned* Qs = sm;                // reused per-warp as P
    unsigned* Kb = sm + TILEW;
    unsigned* Vb = sm + 3 * TILEW;

    const int tid  = threadIdx.x;
    const int warp = tid >> 5, lane = tid & 31;
    const int row  = lane >> 2, t4 = lane & 3;
    const int head = blockIdx.y;
    const int q0   = blockIdx.x * 64;

    int b = 0, fixed = 0, bt = 0;
    if (TMP) { b = blockIdx.z / 28; fixed = blockIdx.z % 28; }
    else     { bt = blockIdx.z; }

    const int Lq    = TMP ? 112 : HWP_;
    const int lastr = min(q0 + 63, Lq - 1);
    const int kmaxb = TMP ? (lastr / 28 + 1) * 28 : HWP_;

    auto stageKV = [&](int buf, int ktt) {
        unsigned* Kd = Kb + buf * TILEW;
        unsigned* Vd = Vb + buf * TILEW;
        for (int f = tid; f < 1024; f += 128) {
            int j = f >> 4, c4 = (f & 15) << 2;
            int kk = min(ktt + j, kmaxb - 1);
            size_t base;
            if (TMP) {
                int nk = (kk / 28) * HWP_ + fixed * fs + (kk % 28) * vs;
                base = (size_t)(b * NN_ + nk) * 1536 + head * HC_ + c4;
            } else {
                base = (size_t)(bt * HWP_ + kk) * 1536 + head * HC_ + c4;
            }
            cpa16(Kd + j * FP + c4, qkv + base + 512);
            cpa16(Vd + j * FP + c4, qkv + base + 1024);
        }
    };

    // ---- stage Q (async) + first K/V tile, one group ----
    for (int f = tid; f < 1024; f += 128) {
        int r = f >> 4, c4 = (f & 15) << 2;
        int rq = min(q0 + r, Lq - 1);
        const float* src;
        if (TMP) {
            int nq = (rq / 28) * HWP_ + fixed * fs + (rq % 28) * vs;
            src = qsrc + (size_t)(b * NN_ + nq) * E_ + head * HC_ + c4;
        } else {
            src = qsrc + (size_t)(bt * HWP_ + rq) * 1536 + head * HC_ + c4;
        }
        cpa16(Qs + r * FP + c4, src);
    }
    stageKV(0, 0);
    asm volatile("cp.async.commit_group;");

    const int r0 = q0 + warp * 16 + row;
    const int lim0 = TMP ? min((r0 / 28 + 1) * 28, 112) : HWP_;
    const int lim1 = TMP ? min(((r0 + 8) / 28 + 1) * 28, 112) : HWP_;
    const int warpLim = TMP ? min(((q0 + warp * 16 + 15) / 28 + 1) * 28, 112) : HWP_;

    unsigned q[8][4];
    float m0 = -1e30f, m1 = -1e30f, l0 = 0.f, l1 = 0.f;
    float4 o[8];
#pragma unroll
    for (int nt = 0; nt < 8; nt++) o[nt] = make_float4(0.f, 0.f, 0.f, 0.f);

    unsigned* Ps = Qs + warp * 16 * FP;

    for (int kt = 0, cur = 0; kt < kmaxb; kt += 64, cur ^= 1) {
        if (kt + 64 < kmaxb) stageKV(cur ^ 1, kt + 64);
        asm volatile("cp.async.commit_group;");      // (possibly empty) group
        asm volatile("cp.async.wait_group 1;");      // current tile complete
        __syncthreads();

        unsigned* Ks = Kb + cur * TILEW;
        unsigned* Vs = Vb + cur * TILEW;

        if (kt == 0) {   // Q resident now; grab fragments before Qs becomes P
            int rm = warp * 16 + row;
#pragma unroll
            for (int kd = 0; kd < 8; kd++) {
                q[kd][0] = Qs[rm * FP + kd * 8 + t4];
                q[kd][1] = Qs[(rm + 8) * FP + kd * 8 + t4];
                q[kd][2] = Qs[rm * FP + kd * 8 + t4 + 4];
                q[kd][3] = Qs[(rm + 8) * FP + kd * 8 + t4 + 4];
            }
        }

        if (kt < warpLim) {
            // ---- S = Q @ K^T ----
            float4 s[8];
#pragma unroll
            for (int nt = 0; nt < 8; nt++) s[nt] = make_float4(0.f, 0.f, 0.f, 0.f);
#pragma unroll
            for (int kd = 0; kd < 8; kd++) {
#pragma unroll
                for (int nt = 0; nt < 8; nt++) {
                    unsigned b0 = Ks[(nt * 8 + row) * FP + kd * 8 + t4];
                    unsigned b1 = Ks[(nt * 8 + row) * FP + kd * 8 + t4 + 4];
                    mma8(s[nt], q[kd], b0, b1);
                }
            }

            // ---- mask + online softmax ----
            if (TMP || kt + 64 > HWP_) {
                int cb = kt + 2 * t4;
#pragma unroll
                for (int nt = 0; nt < 8; nt++) {
                    int c0 = cb + 8 * nt;
                    if (c0     >= lim0) s[nt].x = -1e30f;
                    if (c0 + 1 >= lim0) s[nt].y = -1e30f;
                    if (c0     >= lim1) s[nt].z = -1e30f;
                    if (c0 + 1 >= lim1) s[nt].w = -1e30f;
                }
            }
            float mx0 = -1e30f, mx1 = -1e30f;
#pragma unroll
            for (int nt = 0; nt < 8; nt++) {
                mx0 = fmaxf(mx0, fmaxf(s[nt].x, s[nt].y));
                mx1 = fmaxf(mx1, fmaxf(s[nt].z, s[nt].w));
            }
            mx0 = fmaxf(mx0, __shfl_xor_sync(0xffffffffu, mx0, 1));
            mx0 = fmaxf(mx0, __shfl_xor_sync(0xffffffffu, mx0, 2));
            mx1 = fmaxf(mx1, __shfl_xor_sync(0xffffffffu, mx1, 1));
            mx1 = fmaxf(mx1, __shfl_xor_sync(0xffffffffu, mx1, 2));
            float mn0 = fmaxf(m0, mx0), mn1 = fmaxf(m1, mx1);
            float corr0 = __expf(m0 - mn0), corr1 = __expf(m1 - mn1);
            float ps0 = 0.f, ps1 = 0.f;
#pragma unroll
            for (int nt = 0; nt < 8; nt++) {
                s[nt].x = __expf(s[nt].x - mn0); ps0 += s[nt].x;
                s[nt].y = __expf(s[nt].y - mn0); ps0 += s[nt].y;
                s[nt].z = __expf(s[nt].z - mn1); ps1 += s[nt].z;
                s[nt].w = __expf(s[nt].w - mn1); ps1 += s[nt].w;
            }
            ps0 += __shfl_xor_sync(0xffffffffu, ps0, 1);
            ps0 += __shfl_xor_sync(0xffffffffu, ps0, 2);
            ps1 += __shfl_xor_sync(0xffffffffu, ps1, 1);
            ps1 += __shfl_xor_sync(0xffffffffu, ps1, 2);
            l0 = l0 * corr0 + ps0; l1 = l1 * corr1 + ps1;
            m0 = mn0; m1 = mn1;
#pragma unroll
            for (int nt = 0; nt < 8; nt++) {
                o[nt].x *= corr0; o[nt].y *= corr0;
                o[nt].z *= corr1; o[nt].w *= corr1;
            }

            // ---- store P (warp-private, reuses Q smem) ----
#pragma unroll
            for (int nt = 0; nt < 8; nt++) {
                int c = 8 * nt + 2 * t4;
                *(uint2*)(Ps + row * FP + c)       = make_uint2(f2t(s[nt].x), f2t(s[nt].y));
                *(uint2*)(Ps + (row + 8) * FP + c) = make_uint2(f2t(s[nt].z), f2t(s[nt].w));
            }
            __syncwarp();

            // ---- O += P @ V ----
#pragma unroll
            for (int kk = 0; kk < 8; kk++) {
                unsigned a[4];
                a[0] = Ps[row * FP + kk * 8 + t4];
                a[1] = Ps[(row + 8) * FP + kk * 8 + t4];
                a[2] = Ps[row * FP + kk * 8 + t4 + 4];
                a[3] = Ps[(row + 8) * FP + kk * 8 + t4 + 4];
#pragma unroll
                for (int nt = 0; nt < 8; nt++) {
                    unsigned b0 = Vs[(kk * 8 + t4) * FP + nt * 8 + row];
                    unsigned b1 = Vs[(kk * 8 + t4 + 4) * FP + nt * 8 + row];
                    mma8(o[nt], a, b0, b1);
                }
            }
            __syncwarp();
        }
        __syncthreads();   // all warps done with 'cur' before it is restaged
    }

    // ---- epilogue ----
    float inv0 = 1.f / l0, inv1 = 1.f / l1;
#pragma unroll
    for (int nt = 0; nt < 8; nt++) {
        int dc = nt * 8 + 2 * t4;
        if (r0 < Lq) {
            size_t ob;
            if (TMP) {
                int nq = (r0 / 28) * HWP_ + fixed * fs + (r0 % 28) * vs;
                ob = (size_t)(b * NN_ + nq) * E_ + head * HC_ + dc;
            } else {
                ob = (size_t)(bt * HWP_ + r0) * E_ + head * HC_ + dc;
            }
            float2 res = make_float2(o[nt].x * inv0, o[nt].y * inv0);
            if (TMP && accum) {
                float2 old = *(const float2*)(out + ob);
                res.x += old.x; res.y += old.y;
            }
            *(float2*)(out + ob) = res;
        }
        if (r0 + 8 < Lq) {
            int r1 = r0 + 8;
            size_t ob;
            if (TMP) {
                int nq = (r1 / 28) * HWP_ + fixed * fs + (r1 % 28) * vs;
                ob = (size_t)(b * NN_ + nq) * E_ + head * HC_ + dc;
            } else {
                ob = (size_t)(bt * HWP_ + r1) * E_ + head * HC_ + dc;
            }
            float2 res = make_float2(o[nt].z * inv1, o[nt].w * inv1);
            if (TMP && accum) {
                float2 old = *(const float2*)(out + ob);
                res.x += old.x; res.y += old.y;
            }
            *(float2*)(out + ob) = res;
        }
    }
}

// ---------------------------------------------------------------------------
extern "C" void kernel_launch(void* const* d_in, const int* in_sizes, int n_in,
                              void* d_out, int out_size)
{
    const float* x      = (const float*)d_in[0];
    const float* w_in   = (const float*)d_in[1];
    const float* b_in   = (const float*)d_in[2];
    const float* w_out  = (const float*)d_in[3];
    const float* b_out  = (const float*)d_in[4];
    const float* w_t    = (const float*)d_in[5];
    const float* b_t    = (const float*)d_in[6];
    const float* w_to   = (const float*)d_in[7];
    const float* b_to   = (const float*)d_in[8];
    const float* alpha  = (const float*)d_in[9];
    float* out = (float*)d_out;

    float *qkv, *sp, *qt, *ot;
    cudaGetSymbolAddress((void**)&qkv, g_qkv);
    cudaGetSymbolAddress((void**)&sp,  g_sp);
    cudaGetSymbolAddress((void**)&qt,  g_qt);
    cudaGetSymbolAddress((void**)&ot,  g_ot);

    cudaFuncSetAttribute(flash_tf32<0>, cudaFuncAttributeMaxDynamicSharedMemorySize, FSMEM);
    cudaFuncSetAttribute(flash_tf32<1>, cudaFuncAttributeMaxDynamicSharedMemorySize, FSMEM);

    // 1) qkv projection; q columns pre-scaled, all tf32-rounded
    gemm_tf32<<<dim3(1536 / 128, ROWS_ / 128), 256>>>(
        x, w_in, b_in, qkv, nullptr, ROWS_, 1536, E_, 3, 1.f);

    // 2) spatial attention
    flash_tf32<0><<<dim3(13, NH_, B_ * T_), 128, FSMEM>>>(qkv, qkv, sp, 0, 0, 0);

    // 3) xs = sp @ w_out^T + b_out -> d_out
    gemm_tf32<<<dim3(E_ / 128, ROWS_ / 128), 256>>>(
        sp, w_out, b_out, out, nullptr, ROWS_, E_, E_, 0, 1.f);

    // 4) q_t = (x @ w_t^T + b_t) * scale, tf32-rounded
    gemm_tf32<<<dim3(E_ / 128, ROWS_ / 128), 256>>>(
        x, w_t, b_t, qt, nullptr, ROWS_, E_, E_, 1, SCALE_);

    // 5) temporal-H: ot = o_th
    flash_tf32<1><<<dim3(2, NH_, B_ * 28), 128, FSMEM>>>(qkv, qt, ot, 1, 28, 0);

    // 6) temporal-W: ot += o_tw
    flash_tf32<1><<<dim3(2, NH_, B_ * 28), 128, FSMEM>>>(qkv, qt, ot, 28, 1, 1);

    // 7) out = xs + alpha * (ot @ w_to^T + b_to)
    gemm_tf32<<<dim3(E_ / 128, ROWS_ / 128), 256>>>(
        ot, w_to, b_to, out, alpha, ROWS_, E_, E_, 2, 1.f);
}

// round 5
// speedup vs baseline: 1.2148x; 1.2148x over previous
#include <cuda_runtime.h>
#include <math.h>

#define B_    4
#define T_    4
#define E_    512
#define NH_   8
#define HC_   64
#define HWP_  784
#define NN_   3136
#define ROWS_ 12544
#define SCALE_ 0.125f

__device__ float g_qkv[ROWS_ * 1536];    // q pre-scaled; all tf32-rounded
__device__ float g_sp [ROWS_ * E_];      // tf32-rounded
__device__ float g_qt [ROWS_ * E_];      // pre-scaled, tf32-rounded
__device__ float g_ot [ROWS_ * E_];      // tf32-rounded
__device__ float g_x  [ROWS_ * E_];      // tf32-rounded copy of x
__device__ float g_w1 [2048 * E_];       // rounded concat [w_in; w_t]
__device__ float g_w2 [E_ * E_];         // rounded w_out
__device__ float g_w3 [E_ * E_];         // rounded w_to

__device__ __forceinline__ unsigned f2t(float x) {
    unsigned r; asm("cvt.rna.tf32.f32 %0, %1;" : "=r"(r) : "f"(x)); return r;
}
__device__ __forceinline__ float f2tf(float x) { return __uint_as_float(f2t(x)); }
__device__ __forceinline__ void mma8(float4& d, const unsigned* a, unsigned b0, unsigned b1) {
    asm volatile("mma.sync.aligned.m16n8k8.row.col.f32.tf32.tf32.f32 "
        "{%0,%1,%2,%3},{%4,%5,%6,%7},{%8,%9},{%0,%1,%2,%3};"
        : "+f"(d.x), "+f"(d.y), "+f"(d.z), "+f"(d.w)
        : "r"(a[0]), "r"(a[1]), "r"(a[2]), "r"(a[3]), "r"(b0), "r"(b1));
}
__device__ __forceinline__ void cpa16(void* sdst, const void* gsrc) {
    unsigned s = (unsigned)__cvta_generic_to_shared(sdst);
    asm volatile("cp.async.ca.shared.global [%0], [%1], 16;" :: "r"(s), "l"(gsrc));
}
#define CP_COMMIT() asm volatile("cp.async.commit_group;" ::: "memory")
#define CP_WAIT(n)  asm volatile("cp.async.wait_group %0;" :: "n"(n) : "memory")

// ---------------------------------------------------------------------------
// Prep: tf32-round x and all weights into scratch (one pass, float4).
// ---------------------------------------------------------------------------
#define NX4   (ROWS_ * E_ / 4)      // 1605632
#define NWIN4 (1536 * E_ / 4)       // 196608
#define NW4   (E_ * E_ / 4)         // 65536
#define NPREP (NX4 + NWIN4 + 3 * NW4)

__global__ __launch_bounds__(256)
void prep_round(const float4* __restrict__ x,  const float4* __restrict__ w_in,
                const float4* __restrict__ w_t, const float4* __restrict__ w_out,
                const float4* __restrict__ w_to,
                float4* __restrict__ gx, float4* __restrict__ gw1,
                float4* __restrict__ gw2, float4* __restrict__ gw3)
{
    long i = (long)blockIdx.x * 256 + threadIdx.x;
    const float4* s; float4* d;
    if      (i < NX4)                   { s = x    + i;                       d = gx  + i; }
    else if (i < NX4 + NWIN4)           { long j = i - NX4;                   s = w_in + j;  d = gw1 + j; }
    else if (i < NX4 + NWIN4 + NW4)     { long j = i - NX4 - NWIN4;           s = w_t  + j;  d = gw1 + NWIN4 + j; }
    else if (i < NX4 + NWIN4 + 2*NW4)   { long j = i - NX4 - NWIN4 - NW4;     s = w_out + j; d = gw2 + j; }
    else if (i < NPREP)                 { long j = i - NX4 - NWIN4 - 2*NW4;   s = w_to + j;  d = gw3 + j; }
    else return;
    float4 v = *s;
    v.x = f2tf(v.x); v.y = f2tf(v.y); v.z = f2tf(v.z); v.w = f2tf(v.w);
    *d = v;
}

// ---------------------------------------------------------------------------
// tf32 GEMM v2: 4-stage cp.async pipeline, row-major smem pitch 20.
// C[M,N] = A[M,K] @ W[N,K]^T + bias. All inputs pre-rounded tf32.
// mode 0: C = acc+bias
// mode 2: C = C + alpha[n]*(acc+bias)
// mode 3: merged qkv+qt (N=2048): col<512  -> g_qkv, (v+b_in)*SCALE_, round
//                                 col<1536 -> g_qkv, v+b_in, round
//                                 else     -> C2 (g_qt), (v+b_t)*SCALE_, round
// ---------------------------------------------------------------------------
#define GPITCH 20
#define GSTG   (128 * GPITCH)
#define GSMEM  (8 * GSTG * 4)       // 4 stages x (A+B) = 81920 B

__global__ __launch_bounds__(256, 2)
void gemm_tf32(const float* __restrict__ A, const float* __restrict__ W,
               const float* __restrict__ bias, const float* __restrict__ bias2,
               float* __restrict__ C, float* __restrict__ C2,
               const float* __restrict__ alpha,
               int N, int K, int mode)
{
    extern __shared__ float gsm[];
    float* sA = gsm;
    float* sB = gsm + 4 * GSTG;
    const int bm = blockIdx.y * 128, bn = blockIdx.x * 128;
    const int tid  = threadIdx.x;
    const int warp = tid >> 5, lane = tid & 31;
    const int wm = (warp >> 1) * 32, wn = (warp & 1) * 64;
    const int row = lane >> 2, t4 = lane & 3;

    auto stage = [&](int s, int k0) {
        float* dA = sA + s * GSTG;
        float* dB = sB + s * GSTG;
#pragma unroll
        for (int i = 0; i < 2; i++) {
            int idx = tid * 2 + i;          // 0..511
            int r = idx >> 2, c4 = (idx & 3) << 2;
            cpa16(dA + r * GPITCH + c4, A + (size_t)(bm + r) * K + k0 + c4);
            cpa16(dB + r * GPITCH + c4, W + (size_t)(bn + r) * K + k0 + c4);
        }
    };

    float4 acc[2][8];
#pragma unroll
    for (int i = 0; i < 2; i++)
#pragma unroll
        for (int j = 0; j < 8; j++) acc[i][j] = make_float4(0.f, 0.f, 0.f, 0.f);

    const int nsl = K / 16;     // 32
    stage(0, 0);  CP_COMMIT();
    stage(1, 16); CP_COMMIT();

    for (int i = 0; i < nsl; i++) {
        if (i + 2 < nsl) stage((i + 2) & 3, (i + 2) * 16);
        CP_COMMIT();            // possibly empty group (uniform count)
        CP_WAIT(2);             // slab i resident
        __syncthreads();

        const float* cA = sA + (i & 3) * GSTG;
        const float* cB = sB + (i & 3) * GSTG;
#pragma unroll
        for (int ks = 0; ks < 16; ks += 8) {
            unsigned a[2][4];
#pragma unroll
            for (int mt = 0; mt < 2; mt++) {
                const float* p = cA + (wm + mt * 16 + row) * GPITCH + ks + t4;
                a[mt][0] = __float_as_uint(p[0]);
                a[mt][1] = __float_as_uint(p[8 * GPITCH]);
                a[mt][2] = __float_as_uint(p[4]);
                a[mt][3] = __float_as_uint(p[8 * GPITCH + 4]);
            }
#pragma unroll
            for (int nt = 0; nt < 8; nt++) {
                const float* p = cB + (wn + nt * 8 + row) * GPITCH + ks + t4;
                unsigned b0 = __float_as_uint(p[0]);
                unsigned b1 = __float_as_uint(p[4]);
                mma8(acc[0][nt], a[0], b0, b1);
                mma8(acc[1][nt], a[1], b0, b1);
            }
        }
        // no trailing barrier: 4 stages keep write/read buffers disjoint
    }

#pragma unroll
    for (int mt = 0; mt < 2; mt++) {
        int rg = bm + wm + mt * 16 + row;
#pragma unroll
        for (int nt = 0; nt < 8; nt++) {
            int cg = bn + wn + nt * 8 + 2 * t4;
            float v0 = acc[mt][nt].x, v1 = acc[mt][nt].y;
            float v2 = acc[mt][nt].z, v3 = acc[mt][nt].w;
            if (mode == 3) {
                float bb0, bb1, sc;
                float* dst; int dcol, dstr;
                if (cg < 1536) {
                    bb0 = bias[cg]; bb1 = bias[cg + 1];
                    sc = (cg < E_) ? SCALE_ : 1.f;
                    dst = C; dcol = cg; dstr = 1536;
                } else {
                    bb0 = bias2[cg - 1536]; bb1 = bias2[cg - 1535];
                    sc = SCALE_;
                    dst = C2; dcol = cg - 1536; dstr = E_;
                }
                v0 = f2tf((v0 + bb0) * sc); v1 = f2tf((v1 + bb1) * sc);
                v2 = f2tf((v2 + bb0) * sc); v3 = f2tf((v3 + bb1) * sc);
                *(float2*)(dst + (size_t)rg * dstr + dcol)       = make_float2(v0, v1);
                *(float2*)(dst + (size_t)(rg + 8) * dstr + dcol) = make_float2(v2, v3);
            } else {
                float bb0 = bias[cg], bb1 = bias[cg + 1];
                v0 += bb0; v1 += bb1; v2 += bb0; v3 += bb1;
                size_t i0 = (size_t)rg * N + cg;
                size_t i1 = (size_t)(rg + 8) * N + cg;
                if (mode == 2) {
                    float a0 = alpha[cg], a1 = alpha[cg + 1];
                    float2 o0 = *(const float2*)(C + i0);
                    float2 o1 = *(const float2*)(C + i1);
                    v0 = o0.x + a0 * v0; v1 = o0.y + a1 * v1;
                    v2 = o1.x + a0 * v2; v3 = o1.y + a1 * v3;
                }
                *(float2*)(C + i0) = make_float2(v0, v1);
                *(float2*)(C + i1) = make_float2(v2, v3);
            }
        }
    }
}

// ---------------------------------------------------------------------------
// Flash attention, tf32 mma, cp.async double-buffered K/V.
// 256 threads = 8 warps, BQ=128 (16 rows/warp), key tiles of 64, D=64.
// All inputs pre-rounded tf32 (q pre-scaled). Outputs tf32-rounded.
// smem: Qs/Ps[128][68] | Kb[2][64][68] | Vb[2][64][68]  = 104448 B
// ---------------------------------------------------------------------------
#define FP 68
#define TILEW (64 * FP)
#define FSMEM ((128 * FP + 4 * TILEW) * 4)

template<int TMP>
__global__ __launch_bounds__(256, 2)
void flash_tf32(const float* __restrict__ qkv, const float* __restrict__ qsrc,
                float* __restrict__ out, int fs, int vs, int accum)
{
    extern __shared__ unsigned sm[];
    unsigned* Qs = sm;                  // reused per-warp as P
    unsigned* Kb = sm + 128 * FP;
    unsigned* Vb = Kb + 2 * TILEW;

    const int tid  = threadIdx.x;
    const int warp = tid >> 5, lane = tid & 31;
    const int row  = lane >> 2, t4 = lane & 3;
    const int head = blockIdx.y;
    const int q0   = blockIdx.x * 128;

    int b = 0, fixed = 0, bt = 0;
    if (TMP) { b = blockIdx.z / 28; fixed = blockIdx.z % 28; }
    else     { bt = blockIdx.z; }

    const int Lq    = TMP ? 112 : HWP_;
    const int lastr = min(q0 + 127, Lq - 1);
    const int kmaxb = TMP ? (lastr / 28 + 1) * 28 : HWP_;

    auto stageKV = [&](int buf, int ktt) {
        unsigned* Kd = Kb + buf * TILEW;
        unsigned* Vd = Vb + buf * TILEW;
        for (int f = tid; f < 1024; f += 256) {
            int j = f >> 4, c4 = (f & 15) << 2;
            int kk = min(ktt + j, kmaxb - 1);
            size_t base;
            if (TMP) {
                int nk = (kk / 28) * HWP_ + fixed * fs + (kk % 28) * vs;
                base = (size_t)(b * NN_ + nk) * 1536 + head * HC_ + c4;
            } else {
                base = (size_t)(bt * HWP_ + kk) * 1536 + head * HC_ + c4;
            }
            cpa16(Kd + j * FP + c4, qkv + base + 512);
            cpa16(Vd + j * FP + c4, qkv + base + 1024);
        }
    };

    // ---- stage Q + first K/V tile, one group ----
    for (int f = tid; f < 2048; f += 256) {
        int r = f >> 4, c4 = (f & 15) << 2;
        int rq = min(q0 + r, Lq - 1);
        const float* src;
        if (TMP) {
            int nq = (rq / 28) * HWP_ + fixed * fs + (rq % 28) * vs;
            src = qsrc + (size_t)(b * NN_ + nq) * E_ + head * HC_ + c4;
        } else {
            src = qsrc + (size_t)(bt * HWP_ + rq) * 1536 + head * HC_ + c4;
        }
        cpa16(Qs + r * FP + c4, src);
    }
    stageKV(0, 0);
    CP_COMMIT();

    const int r0 = q0 + warp * 16 + row;
    const int lim0 = TMP ? min((r0 / 28 + 1) * 28, 112) : HWP_;
    const int lim1 = TMP ? min(((r0 + 8) / 28 + 1) * 28, 112) : HWP_;
    const int warpLim = TMP ? min(((q0 + warp * 16 + 15) / 28 + 1) * 28, 112) : HWP_;

    unsigned q[8][4];
    float m0 = -1e30f, m1 = -1e30f, l0 = 0.f, l1 = 0.f;
    float4 o[8];
#pragma unroll
    for (int nt = 0; nt < 8; nt++) o[nt] = make_float4(0.f, 0.f, 0.f, 0.f);

    unsigned* Ps = Qs + warp * 16 * FP;

    for (int kt = 0, cur = 0; kt < kmaxb; kt += 64, cur ^= 1) {
        if (kt + 64 < kmaxb) stageKV(cur ^ 1, kt + 64);
        CP_COMMIT();
        CP_WAIT(1);
        __syncthreads();

        unsigned* Ks = Kb + cur * TILEW;
        unsigned* Vs = Vb + cur * TILEW;

        if (kt == 0) {      // Q resident; grab fragments before Qs becomes P
            int rm = warp * 16 + row;
#pragma unroll
            for (int kd = 0; kd < 8; kd++) {
                q[kd][0] = Qs[rm * FP + kd * 8 + t4];
                q[kd][1] = Qs[(rm + 8) * FP + kd * 8 + t4];
                q[kd][2] = Qs[rm * FP + kd * 8 + t4 + 4];
                q[kd][3] = Qs[(rm + 8) * FP + kd * 8 + t4 + 4];
            }
        }

        if (kt < warpLim) {
            float4 s[8];
#pragma unroll
            for (int nt = 0; nt < 8; nt++) s[nt] = make_float4(0.f, 0.f, 0.f, 0.f);
#pragma unroll
            for (int kd = 0; kd < 8; kd++) {
#pragma unroll
                for (int nt = 0; nt < 8; nt++) {
                    unsigned b0 = Ks[(nt * 8 + row) * FP + kd * 8 + t4];
                    unsigned b1 = Ks[(nt * 8 + row) * FP + kd * 8 + t4 + 4];
                    mma8(s[nt], q[kd], b0, b1);
                }
            }

            if (TMP || kt + 64 > HWP_) {
                int cb = kt + 2 * t4;
#pragma unroll
                for (int nt = 0; nt < 8; nt++) {
                    int c0 = cb + 8 * nt;
                    if (c0     >= lim0) s[nt].x = -1e30f;
                    if (c0 + 1 >= lim0) s[nt].y = -1e30f;
                    if (c0     >= lim1) s[nt].z = -1e30f;
                    if (c0 + 1 >= lim1) s[nt].w = -1e30f;
                }
            }
            float mx0 = -1e30f, mx1 = -1e30f;
#pragma unroll
            for (int nt = 0; nt < 8; nt++) {
                mx0 = fmaxf(mx0, fmaxf(s[nt].x, s[nt].y));
                mx1 = fmaxf(mx1, fmaxf(s[nt].z, s[nt].w));
            }
            mx0 = fmaxf(mx0, __shfl_xor_sync(0xffffffffu, mx0, 1));
            mx0 = fmaxf(mx0, __shfl_xor_sync(0xffffffffu, mx0, 2));
            mx1 = fmaxf(mx1, __shfl_xor_sync(0xffffffffu, mx1, 1));
            mx1 = fmaxf(mx1, __shfl_xor_sync(0xffffffffu, mx1, 2));
            float mn0 = fmaxf(m0, mx0), mn1 = fmaxf(m1, mx1);
            float corr0 = __expf(m0 - mn0), corr1 = __expf(m1 - mn1);
            float ps0 = 0.f, ps1 = 0.f;
#pragma unroll
            for (int nt = 0; nt < 8; nt++) {
                s[nt].x = __expf(s[nt].x - mn0); ps0 += s[nt].x;
                s[nt].y = __expf(s[nt].y - mn0); ps0 += s[nt].y;
                s[nt].z = __expf(s[nt].z - mn1); ps1 += s[nt].z;
                s[nt].w = __expf(s[nt].w - mn1); ps1 += s[nt].w;
            }
            ps0 += __shfl_xor_sync(0xffffffffu, ps0, 1);
            ps0 += __shfl_xor_sync(0xffffffffu, ps0, 2);
            ps1 += __shfl_xor_sync(0xffffffffu, ps1, 1);
            ps1 += __shfl_xor_sync(0xffffffffu, ps1, 2);
            l0 = l0 * corr0 + ps0; l1 = l1 * corr1 + ps1;
            m0 = mn0; m1 = mn1;
#pragma unroll
            for (int nt = 0; nt < 8; nt++) {
                o[nt].x *= corr0; o[nt].y *= corr0;
                o[nt].z *= corr1; o[nt].w *= corr1;
            }

#pragma unroll
            for (int nt = 0; nt < 8; nt++) {
                int c = 8 * nt + 2 * t4;
                *(uint2*)(Ps + row * FP + c)       = make_uint2(f2t(s[nt].x), f2t(s[nt].y));
                *(uint2*)(Ps + (row + 8) * FP + c) = make_uint2(f2t(s[nt].z), f2t(s[nt].w));
            }
            __syncwarp();

#pragma unroll
            for (int kk = 0; kk < 8; kk++) {
                unsigned a[4];
                a[0] = Ps[row * FP + kk * 8 + t4];
                a[1] = Ps[(row + 8) * FP + kk * 8 + t4];
                a[2] = Ps[row * FP + kk * 8 + t4 + 4];
                a[3] = Ps[(row + 8) * FP + kk * 8 + t4 + 4];
#pragma unroll
                for (int nt = 0; nt < 8; nt++) {
                    unsigned b0 = Vs[(kk * 8 + t4) * FP + nt * 8 + row];
                    unsigned b1 = Vs[(kk * 8 + t4 + 4) * FP + nt * 8 + row];
                    mma8(o[nt], a, b0, b1);
                }
            }
            __syncwarp();
        }
        __syncthreads();    // all warps done with 'cur' before restage
    }

    // ---- epilogue: normalize, tf32-round, (accumulate), store ----
    float inv0 = 1.f / l0, inv1 = 1.f / l1;
#pragma unroll
    for (int nt = 0; nt < 8; nt++) {
        int dc = nt * 8 + 2 * t4;
        if (r0 < Lq) {
            size_t ob;
            if (TMP) {
                int nq = (r0 / 28) * HWP_ + fixed * fs + (r0 % 28) * vs;
                ob = (size_t)(b * NN_ + nq) * E_ + head * HC_ + dc;
            } else {
                ob = (size_t)(bt * HWP_ + r0) * E_ + head * HC_ + dc;
            }
            float rx = o[nt].x * inv0, ry = o[nt].y * inv0;
            if (TMP && accum) {
                float2 old = *(const float2*)(out + ob);
                rx += old.x; ry += old.y;
            }
            *(float2*)(out + ob) = make_float2(f2tf(rx), f2tf(ry));
        }
        if (r0 + 8 < Lq) {
            int r1 = r0 + 8;
            size_t ob;
            if (TMP) {
                int nq = (r1 / 28) * HWP_ + fixed * fs + (r1 % 28) * vs;
                ob = (size_t)(b * NN_ + nq) * E_ + head * HC_ + dc;
            } else {
                ob = (size_t)(bt * HWP_ + r1) * E_ + head * HC_ + dc;
            }
            float rx = o[nt].z * inv1, ry = o[nt].w * inv1;
            if (TMP && accum) {
                float2 old = *(const float2*)(out + ob);
                rx += old.x; ry += old.y;
            }
            *(float2*)(out + ob) = make_float2(f2tf(rx), f2tf(ry));
        }
    }
}

// ---------------------------------------------------------------------------
extern "C" void kernel_launch(void* const* d_in, const int* in_sizes, int n_in,
                              void* d_out, int out_size)
{
    const float* x      = (const float*)d_in[0];
    const float* w_in   = (const float*)d_in[1];
    const float* b_in   = (const float*)d_in[2];
    const float* w_out  = (const float*)d_in[3];
    const float* b_out  = (const float*)d_in[4];
    const float* w_t    = (const float*)d_in[5];
    const float* b_t    = (const float*)d_in[6];
    const float* w_to   = (const float*)d_in[7];
    const float* b_to   = (const float*)d_in[8];
    const float* alpha  = (const float*)d_in[9];
    float* out = (float*)d_out;

    float *qkv, *sp, *qt, *ot, *gx, *gw1, *gw2, *gw3;
    cudaGetSymbolAddress((void**)&qkv, g_qkv);
    cudaGetSymbolAddress((void**)&sp,  g_sp);
    cudaGetSymbolAddress((void**)&qt,  g_qt);
    cudaGetSymbolAddress((void**)&ot,  g_ot);
    cudaGetSymbolAddress((void**)&gx,  g_x);
    cudaGetSymbolAddress((void**)&gw1, g_w1);
    cudaGetSymbolAddress((void**)&gw2, g_w2);
    cudaGetSymbolAddress((void**)&gw3, g_w3);

    cudaFuncSetAttribute(gemm_tf32,   cudaFuncAttributeMaxDynamicSharedMemorySize, GSMEM);
    cudaFuncSetAttribute(flash_tf32<0>, cudaFuncAttributeMaxDynamicSharedMemorySize, FSMEM);
    cudaFuncSetAttribute(flash_tf32<1>, cudaFuncAttributeMaxDynamicSharedMemorySize, FSMEM);

    // 0) tf32-round x + weights into scratch
    prep_round<<<NPREP / 256, 256>>>(
        (const float4*)x, (const float4*)w_in, (const float4*)w_t,
        (const float4*)w_out, (const float4*)w_to,
        (float4*)gx, (float4*)gw1, (float4*)gw2, (float4*)gw3);

    // 1) merged qkv + qt projection (N=2048)
    gemm_tf32<<<dim3(16, 98), 256, GSMEM>>>(
        gx, gw1, b_in, b_t, qkv, qt, nullptr, 2048, E_, 3);

    // 2) spatial attention -> sp (rounded)
    flash_tf32<0><<<dim3(7, NH_, B_ * T_), 256, FSMEM>>>(qkv, qkv, sp, 0, 0, 0);

    // 3) xs = sp @ w_out^T + b_out -> out
    gemm_tf32<<<dim3(4, 98), 256, GSMEM>>>(
        sp, gw2, b_out, nullptr, out, nullptr, nullptr, E_, E_, 0);

    // 4) temporal-H: ot = o_th (rounded)
    flash_tf32<1><<<dim3(1, NH_, B_ * 28), 256, FSMEM>>>(qkv, qt, ot, 1, 28, 0);

    // 5) temporal-W: ot += o_tw (rounded)
    flash_tf32<1><<<dim3(1, NH_, B_ * 28), 256, FSMEM>>>(qkv, qt, ot, 28, 1, 1);

    // 6) out = xs + alpha * (ot @ w_to^T + b_to)
    gemm_tf32<<<dim3(4, 98), 256, GSMEM>>>(
        ot, gw3, b_to, nullptr, out, nullptr, alpha, E_, E_, 2);
}

// round 6
// speedup vs baseline: 1.2572x; 1.0349x over previous
#include <cuda_runtime.h>
#include <math.h>

#define B_    4
#define T_    4
#define E_    512
#define NH_   8
#define HC_   64
#define HWP_  784
#define NN_   3136
#define ROWS_ 12544
#define SCALE_ 0.125f

// All K-dims in scratch use the sigma permutation within each 8-group:
// stored position sigma(j) = 2*(j&3) + (j>>2) holds true dim j.
__device__ float g_qkv[ROWS_ * 1536];
__device__ float g_sp [ROWS_ * E_];
__device__ float g_qt [ROWS_ * E_];
__device__ float g_ot [ROWS_ * E_];
__device__ float g_x  [ROWS_ * E_];
__device__ float g_w1 [2048 * E_];
__device__ float g_w2 [E_ * E_];
__device__ float g_w3 [E_ * E_];

__device__ __forceinline__ unsigned f2t(float x) {
    unsigned r; asm("cvt.rna.tf32.f32 %0, %1;" : "=r"(r) : "f"(x)); return r;
}
__device__ __forceinline__ float f2tf(float x) { return __uint_as_float(f2t(x)); }
__device__ __forceinline__ void mma8(float4& d, const unsigned* a, unsigned b0, unsigned b1) {
    asm volatile("mma.sync.aligned.m16n8k8.row.col.f32.tf32.tf32.f32 "
        "{%0,%1,%2,%3},{%4,%5,%6,%7},{%8,%9},{%0,%1,%2,%3};"
        : "+f"(d.x), "+f"(d.y), "+f"(d.z), "+f"(d.w)
        : "r"(a[0]), "r"(a[1]), "r"(a[2]), "r"(a[3]), "r"(b0), "r"(b1));
}
__device__ __forceinline__ void cpa16(void* sdst, const void* gsrc) {
    unsigned s = (unsigned)__cvta_generic_to_shared(sdst);
    asm volatile("cp.async.ca.shared.global [%0], [%1], 16;" :: "r"(s), "l"(gsrc));
}
#define CP_COMMIT() asm volatile("cp.async.commit_group;" ::: "memory")
#define CP_WAIT(n)  asm volatile("cp.async.wait_group %0;" :: "n"(n) : "memory")

// ---------------------------------------------------------------------------
// Prep: tf32-round + sigma-permute (per 8-group of the fast K dim)
// x and all weights into scratch. Each thread handles one 8-group.
// out[sigma(j)] = in[j]: o0 = (i0.x, i1.x, i0.y, i1.y), o1 = (i0.z,i1.z,i0.w,i1.w)
// ---------------------------------------------------------------------------
#define NX8   (ROWS_ * E_ / 8)     // 802816
#define NW18  (1536 * E_ / 8)      // 98304
#define NW8   (E_ * E_ / 8)        // 32768
#define NPREPG (NX8 + NW18 + 3 * NW8)   // 999424 (divisible by 256)

__global__ __launch_bounds__(256)
void prep_round(const float4* __restrict__ x,  const float4* __restrict__ w_in,
                const float4* __restrict__ w_t, const float4* __restrict__ w_out,
                const float4* __restrict__ w_to,
                float4* __restrict__ gx, float4* __restrict__ gw1,
                float4* __restrict__ gw2, float4* __restrict__ gw3)
{
    long i = (long)blockIdx.x * 256 + threadIdx.x;   // group index
    const float4* s; float4* d;
    if      (i < NX8)                { s = x + 2*i;                     d = gx + 2*i; }
    else if (i < NX8 + NW18)         { long j = i - NX8;                s = w_in + 2*j;  d = gw1 + 2*j; }
    else if (i < NX8 + NW18 + NW8)   { long j = i - NX8 - NW18;         s = w_t + 2*j;   d = gw1 + 2*(NW18 + j); }
    else if (i < NX8 + NW18 + 2*NW8) { long j = i - NX8 - NW18 - NW8;   s = w_out + 2*j; d = gw2 + 2*j; }
    else if (i < NPREPG)             { long j = i - NX8 - NW18 - 2*NW8; s = w_to + 2*j;  d = gw3 + 2*j; }
    else return;
    float4 i0 = s[0], i1 = s[1];
    float4 o0 = make_float4(f2tf(i0.x), f2tf(i1.x), f2tf(i0.y), f2tf(i1.y));
    float4 o1 = make_float4(f2tf(i0.z), f2tf(i1.z), f2tf(i0.w), f2tf(i1.w));
    d[0] = o0; d[1] = o1;
}

// ---------------------------------------------------------------------------
// tf32 GEMM: 4-stage cp.async, pitch 24, LDS.64 fragment loads (sigma layout).
// C[M,N] = A[M,K] @ W[N,K]^T + bias, A/W K-dims sigma-permuted identically.
// mode 0: C = acc+bias (true layout)
// mode 2: C = C + alpha[n]*(acc+bias) (true layout)
// mode 3: merged qkv+qt (N=2048), outputs stored sigma-permuted per 8-group:
//         col<512 -> qkv q (*SCALE_), col<1536 -> qkv k/v, else -> qt (*SCALE_)
// ---------------------------------------------------------------------------
#define GPITCH 24
#define GSTG   (128 * GPITCH)
#define GSMEM  (8 * GSTG * 4)       // 98304 B

__global__ __launch_bounds__(256, 2)
void gemm_tf32(const float* __restrict__ A, const float* __restrict__ W,
               const float* __restrict__ bias, const float* __restrict__ bias2,
               float* __restrict__ C, float* __restrict__ C2,
               const float* __restrict__ alpha,
               int N, int K, int mode)
{
    extern __shared__ float gsm[];
    float* sA = gsm;
    float* sB = gsm + 4 * GSTG;
    const int bm = blockIdx.y * 128, bn = blockIdx.x * 128;
    const int tid  = threadIdx.x;
    const int warp = tid >> 5, lane = tid & 31;
    const int wm = (warp >> 1) * 32, wn = (warp & 1) * 64;
    const int row = lane >> 2, t4 = lane & 3;

    auto stage = [&](int s, int k0) {
        float* dA = sA + s * GSTG;
        float* dB = sB + s * GSTG;
#pragma unroll
        for (int i = 0; i < 2; i++) {
            int idx = tid * 2 + i;
            int r = idx >> 2, c4 = (idx & 3) << 2;
            cpa16(dA + r * GPITCH + c4, A + (size_t)(bm + r) * K + k0 + c4);
            cpa16(dB + r * GPITCH + c4, W + (size_t)(bn + r) * K + k0 + c4);
        }
    };

    float4 acc[2][8];
#pragma unroll
    for (int i = 0; i < 2; i++)
#pragma unroll
        for (int j = 0; j < 8; j++) acc[i][j] = make_float4(0.f, 0.f, 0.f, 0.f);

    const int nsl = K / 16;
    stage(0, 0);  CP_COMMIT();
    stage(1, 16); CP_COMMIT();

    for (int i = 0; i < nsl; i++) {
        if (i + 2 < nsl) stage((i + 2) & 3, (i + 2) * 16);
        CP_COMMIT();
        CP_WAIT(2);
        __syncthreads();

        const float* cA = sA + (i & 3) * GSTG;
        const float* cB = sB + (i & 3) * GSTG;
#pragma unroll
        for (int ks = 0; ks < 16; ks += 8) {
            unsigned a[2][4];
#pragma unroll
            for (int mt = 0; mt < 2; mt++) {
                const float* p = cA + (wm + mt * 16 + row) * GPITCH + ks + 2 * t4;
                uint2 u0 = *(const uint2*)p;
                uint2 u1 = *(const uint2*)(p + 8 * GPITCH);
                a[mt][0] = u0.x; a[mt][1] = u1.x; a[mt][2] = u0.y; a[mt][3] = u1.y;
            }
#pragma unroll
            for (int nt = 0; nt < 8; nt++) {
                uint2 ub = *(const uint2*)(cB + (wn + nt * 8 + row) * GPITCH + ks + 2 * t4);
                mma8(acc[0][nt], a[0], ub.x, ub.y);
                mma8(acc[1][nt], a[1], ub.x, ub.y);
            }
        }
    }

#pragma unroll
    for (int mt = 0; mt < 2; mt++) {
        int rg = bm + wm + mt * 16 + row;
#pragma unroll
        for (int nt = 0; nt < 8; nt++) {
            int cg = bn + wn + nt * 8 + 2 * t4;
            float v0 = acc[mt][nt].x, v1 = acc[mt][nt].y;
            float v2 = acc[mt][nt].z, v3 = acc[mt][nt].w;
            if (mode == 3) {
                float bb0, bb1, sc;
                float* dst; int off, dstr;
                if (cg < 1536) {
                    bb0 = bias[cg]; bb1 = bias[cg + 1];
                    sc = (cg < E_) ? SCALE_ : 1.f;
                    dst = C; off = 0; dstr = 1536;
                } else {
                    bb0 = bias2[cg - 1536]; bb1 = bias2[cg - 1535];
                    sc = SCALE_;
                    dst = C2; off = 1536; dstr = E_;
                }
                v0 = f2tf((v0 + bb0) * sc); v1 = f2tf((v1 + bb1) * sc);
                v2 = f2tf((v2 + bb0) * sc); v3 = f2tf((v3 + bb1) * sc);
                int g8 = cg & ~7, j0 = cg & 7;
                int p0 = g8 + ((j0 & 3) * 2 + (j0 >> 2)) - off;
                int p1 = g8 + (((j0 + 1) & 3) * 2 + ((j0 + 1) >> 2)) - off;
                dst[(size_t)rg * dstr + p0]       = v0;
                dst[(size_t)rg * dstr + p1]       = v1;
                dst[(size_t)(rg + 8) * dstr + p0] = v2;
                dst[(size_t)(rg + 8) * dstr + p1] = v3;
            } else {
                float bb0 = bias[cg], bb1 = bias[cg + 1];
                v0 += bb0; v1 += bb1; v2 += bb0; v3 += bb1;
                size_t i0 = (size_t)rg * N + cg;
                size_t i1 = (size_t)(rg + 8) * N + cg;
                if (mode == 2) {
                    float a0 = alpha[cg], a1 = alpha[cg + 1];
                    float2 o0 = *(const float2*)(C + i0);
                    float2 o1 = *(const float2*)(C + i1);
                    v0 = o0.x + a0 * v0; v1 = o0.y + a1 * v1;
                    v2 = o1.x + a0 * v2; v3 = o1.y + a1 * v3;
                }
                *(float2*)(C + i0) = make_float2(v0, v1);
                *(float2*)(C + i1) = make_float2(v2, v3);
            }
        }
    }
}

// ---------------------------------------------------------------------------
// Flash attention, tf32 mma, cp.async double-buffered K/V, sigma-permuted dims.
// 256 threads = 8 warps, BQ=128 (16 rows/warp), key tiles of 64, D=64.
// Q/K dims sigma-permuted -> LDS.64 fragment pairs. V dims permuted -> O cols
// come out in permuted space, matching the next GEMM's expectation.
// smem: Qs/Ps[128][68] | Kb[2][64][72] | Vb[2][64][72]  = 108544 B
// ---------------------------------------------------------------------------
#define FP  68
#define FPK 72
#define KTILE (64 * FPK)
#define FSMEM ((128 * FP + 4 * KTILE) * 4)

template<int TMP>
__global__ __launch_bounds__(256, 2)
void flash_tf32(const float* __restrict__ qkv, const float* __restrict__ qsrc,
                float* __restrict__ out, int fs, int vs, int accum)
{
    extern __shared__ unsigned sm[];
    unsigned* Qs = sm;                  // reused per-warp as P
    unsigned* Kb = sm + 128 * FP;
    unsigned* Vb = Kb + 2 * KTILE;

    const int tid  = threadIdx.x;
    const int warp = tid >> 5, lane = tid & 31;
    const int row  = lane >> 2, t4 = lane & 3;
    const int head = blockIdx.y;
    const int q0   = blockIdx.x * 128;

    int b = 0, fixed = 0, bt = 0;
    if (TMP) { b = blockIdx.z / 28; fixed = blockIdx.z % 28; }
    else     { bt = blockIdx.z; }

    const int Lq    = TMP ? 112 : HWP_;
    const int lastr = min(q0 + 127, Lq - 1);
    const int kmaxb = TMP ? (lastr / 28 + 1) * 28 : HWP_;

    auto stageKV = [&](int buf, int ktt) {
        unsigned* Kd = Kb + buf * KTILE;
        unsigned* Vd = Vb + buf * KTILE;
        for (int f = tid; f < 1024; f += 256) {
            int j = f >> 4, c4 = (f & 15) << 2;
            int kk = min(ktt + j, kmaxb - 1);
            size_t base;
            if (TMP) {
                int nk = (kk / 28) * HWP_ + fixed * fs + (kk % 28) * vs;
                base = (size_t)(b * NN_ + nk) * 1536 + head * HC_ + c4;
            } else {
                base = (size_t)(bt * HWP_ + kk) * 1536 + head * HC_ + c4;
            }
            cpa16(Kd + j * FPK + c4, qkv + base + 512);
            cpa16(Vd + j * FPK + c4, qkv + base + 1024);
        }
    };

    for (int f = tid; f < 2048; f += 256) {
        int r = f >> 4, c4 = (f & 15) << 2;
        int rq = min(q0 + r, Lq - 1);
        const float* src;
        if (TMP) {
            int nq = (rq / 28) * HWP_ + fixed * fs + (rq % 28) * vs;
            src = qsrc + (size_t)(b * NN_ + nq) * E_ + head * HC_ + c4;
        } else {
            src = qsrc + (size_t)(bt * HWP_ + rq) * 1536 + head * HC_ + c4;
        }
        cpa16(Qs + r * FP + c4, src);
    }
    stageKV(0, 0);
    CP_COMMIT();

    const int r0 = q0 + warp * 16 + row;
    const int lim0 = TMP ? min((r0 / 28 + 1) * 28, 112) : HWP_;
    const int lim1 = TMP ? min(((r0 + 8) / 28 + 1) * 28, 112) : HWP_;
    const int warpLim = TMP ? min(((q0 + warp * 16 + 15) / 28 + 1) * 28, 112) : HWP_;

    unsigned q[8][4];
    float m0 = -1e30f, m1 = -1e30f, l0 = 0.f, l1 = 0.f;
    float4 o[8];
#pragma unroll
    for (int nt = 0; nt < 8; nt++) o[nt] = make_float4(0.f, 0.f, 0.f, 0.f);

    unsigned* Ps = Qs + warp * 16 * FP;

    for (int kt = 0, cur = 0; kt < kmaxb; kt += 64, cur ^= 1) {
        if (kt + 64 < kmaxb) stageKV(cur ^ 1, kt + 64);
        CP_COMMIT();
        CP_WAIT(1);
        __syncthreads();

        unsigned* Ks = Kb + cur * KTILE;
        unsigned* Vs = Vb + cur * KTILE;

        if (kt == 0) {
            int rm = warp * 16 + row;
#pragma unroll
            for (int kd = 0; kd < 8; kd++) {
                uint2 u0 = *(const uint2*)(Qs + rm * FP + kd * 8 + 2 * t4);
                uint2 u1 = *(const uint2*)(Qs + (rm + 8) * FP + kd * 8 + 2 * t4);
                q[kd][0] = u0.x; q[kd][1] = u1.x; q[kd][2] = u0.y; q[kd][3] = u1.y;
            }
        }

        if (kt < warpLim) {
            float4 s[8];
#pragma unroll
            for (int nt = 0; nt < 8; nt++) s[nt] = make_float4(0.f, 0.f, 0.f, 0.f);
#pragma unroll
            for (int kd = 0; kd < 8; kd++) {
#pragma unroll
                for (int nt = 0; nt < 8; nt++) {
                    uint2 ub = *(const uint2*)(Ks + (nt * 8 + row) * FPK + kd * 8 + 2 * t4);
                    mma8(s[nt], q[kd], ub.x, ub.y);
                }
            }

            if (TMP || kt + 64 > HWP_) {
                int cb = kt + 2 * t4;
#pragma unroll
                for (int nt = 0; nt < 8; nt++) {
                    int c0 = cb + 8 * nt;
                    if (c0     >= lim0) s[nt].x = -1e30f;
                    if (c0 + 1 >= lim0) s[nt].y = -1e30f;
                    if (c0     >= lim1) s[nt].z = -1e30f;
                    if (c0 + 1 >= lim1) s[nt].w = -1e30f;
                }
            }
            float mx0 = -1e30f, mx1 = -1e30f;
#pragma unroll
            for (int nt = 0; nt < 8; nt++) {
                mx0 = fmaxf(mx0, fmaxf(s[nt].x, s[nt].y));
                mx1 = fmaxf(mx1, fmaxf(s[nt].z, s[nt].w));
            }
            mx0 = fmaxf(mx0, __shfl_xor_sync(0xffffffffu, mx0, 1));
            mx0 = fmaxf(mx0, __shfl_xor_sync(0xffffffffu, mx0, 2));
            mx1 = fmaxf(mx1, __shfl_xor_sync(0xffffffffu, mx1, 1));
            mx1 = fmaxf(mx1, __shfl_xor_sync(0xffffffffu, mx1, 2));
            float mn0 = fmaxf(m0, mx0), mn1 = fmaxf(m1, mx1);
            float corr0 = __expf(m0 - mn0), corr1 = __expf(m1 - mn1);
            float ps0 = 0.f, ps1 = 0.f;
#pragma unroll
            for (int nt = 0; nt < 8; nt++) {
                s[nt].x = __expf(s[nt].x - mn0); ps0 += s[nt].x;
                s[nt].y = __expf(s[nt].y - mn0); ps0 += s[nt].y;
                s[nt].z = __expf(s[nt].z - mn1); ps1 += s[nt].z;
                s[nt].w = __expf(s[nt].w - mn1); ps1 += s[nt].w;
            }
            ps0 += __shfl_xor_sync(0xffffffffu, ps0, 1);
            ps0 += __shfl_xor_sync(0xffffffffu, ps0, 2);
            ps1 += __shfl_xor_sync(0xffffffffu, ps1, 1);
            ps1 += __shfl_xor_sync(0xffffffffu, ps1, 2);
            l0 = l0 * corr0 + ps0; l1 = l1 * corr1 + ps1;
            m0 = mn0; m1 = mn1;
#pragma unroll
            for (int nt = 0; nt < 8; nt++) {
                o[nt].x *= corr0; o[nt].y *= corr0;
                o[nt].z *= corr1; o[nt].w *= corr1;
            }

#pragma unroll
            for (int nt = 0; nt < 8; nt++) {
                int c = 8 * nt + 2 * t4;
                *(uint2*)(Ps + row * FP + c)       = make_uint2(f2t(s[nt].x), f2t(s[nt].y));
                *(uint2*)(Ps + (row + 8) * FP + c) = make_uint2(f2t(s[nt].z), f2t(s[nt].w));
            }
            __syncwarp();

#pragma unroll
            for (int kk = 0; kk < 8; kk++) {
                unsigned a[4];
                a[0] = Ps[row * FP + kk * 8 + t4];
                a[1] = Ps[(row + 8) * FP + kk * 8 + t4];
                a[2] = Ps[row * FP + kk * 8 + t4 + 4];
                a[3] = Ps[(row + 8) * FP + kk * 8 + t4 + 4];
#pragma unroll
                for (int nt = 0; nt < 8; nt++) {
                    unsigned b0 = Vs[(kk * 8 + t4) * FPK + nt * 8 + row];
                    unsigned b1 = Vs[(kk * 8 + t4 + 4) * FPK + nt * 8 + row];
                    mma8(o[nt], a, b0, b1);
                }
            }
            __syncwarp();
        }
        __syncthreads();
    }

    float inv0 = 1.f / l0, inv1 = 1.f / l1;
#pragma unroll
    for (int nt = 0; nt < 8; nt++) {
        int dc = nt * 8 + 2 * t4;
        if (r0 < Lq) {
            size_t ob;
            if (TMP) {
                int nq = (r0 / 28) * HWP_ + fixed * fs + (r0 % 28) * vs;
                ob = (size_t)(b * NN_ + nq) * E_ + head * HC_ + dc;
            } else {
                ob = (size_t)(bt * HWP_ + r0) * E_ + head * HC_ + dc;
            }
            float rx = o[nt].x * inv0, ry = o[nt].y * inv0;
            if (TMP && accum) {
                float2 old = *(const float2*)(out + ob);
                rx += old.x; ry += old.y;
            }
            *(float2*)(out + ob) = make_float2(f2tf(rx), f2tf(ry));
        }
        if (r0 + 8 < Lq) {
            int r1 = r0 + 8;
            size_t ob;
            if (TMP) {
                int nq = (r1 / 28) * HWP_ + fixed * fs + (r1 % 28) * vs;
                ob = (size_t)(b * NN_ + nq) * E_ + head * HC_ + dc;
            } else {
                ob = (size_t)(bt * HWP_ + r1) * E_ + head * HC_ + dc;
            }
            float rx = o[nt].z * inv1, ry = o[nt].w * inv1;
            if (TMP && accum) {
                float2 old = *(const float2*)(out + ob);
                rx += old.x; ry += old.y;
            }
            *(float2*)(out + ob) = make_float2(f2tf(rx), f2tf(ry));
        }
    }
}

// ---------------------------------------------------------------------------
extern "C" void kernel_launch(void* const* d_in, const int* in_sizes, int n_in,
                              void* d_out, int out_size)
{
    const float* x      = (const float*)d_in[0];
    const float* w_in   = (const float*)d_in[1];
    const float* b_in   = (const float*)d_in[2];
    const float* w_out  = (const float*)d_in[3];
    const float* b_out  = (const float*)d_in[4];
    const float* w_t    = (const float*)d_in[5];
    const float* b_t    = (const float*)d_in[6];
    const float* w_to   = (const float*)d_in[7];
    const float* b_to   = (const float*)d_in[8];
    const float* alpha  = (const float*)d_in[9];
    float* out = (float*)d_out;

    float *qkv, *sp, *qt, *ot, *gx, *gw1, *gw2, *gw3;
    cudaGetSymbolAddress((void**)&qkv, g_qkv);
    cudaGetSymbolAddress((void**)&sp,  g_sp);
    cudaGetSymbolAddress((void**)&qt,  g_qt);
    cudaGetSymbolAddress((void**)&ot,  g_ot);
    cudaGetSymbolAddress((void**)&gx,  g_x);
    cudaGetSymbolAddress((void**)&gw1, g_w1);
    cudaGetSymbolAddress((void**)&gw2, g_w2);
    cudaGetSymbolAddress((void**)&gw3, g_w3);

    cudaFuncSetAttribute(gemm_tf32,     cudaFuncAttributeMaxDynamicSharedMemorySize, GSMEM);
    cudaFuncSetAttribute(flash_tf32<0>, cudaFuncAttributeMaxDynamicSharedMemorySize, FSMEM);
    cudaFuncSetAttribute(flash_tf32<1>, cudaFuncAttributeMaxDynamicSharedMemorySize, FSMEM);

    // 0) tf32-round + sigma-permute x + weights
    prep_round<<<NPREPG / 256, 256>>>(
        (const float4*)x, (const float4*)w_in, (const float4*)w_t,
        (const float4*)w_out, (const float4*)w_to,
        (float4*)gx, (float4*)gw1, (float4*)gw2, (float4*)gw3);

    // 1) merged qkv + qt projection (N=2048), outputs sigma-permuted
    gemm_tf32<<<dim3(16, 98), 256, GSMEM>>>(
        gx, gw1, b_in, b_t, qkv, qt, nullptr, 2048, E_, 3);

    // 2) spatial attention -> sp (permuted space)
    flash_tf32<0><<<dim3(7, NH_, B_ * T_), 256, FSMEM>>>(qkv, qkv, sp, 0, 0, 0);

    // 3) xs = sp @ w_out^T + b_out -> out (true layout)
    gemm_tf32<<<dim3(4, 98), 256, GSMEM>>>(
        sp, gw2, b_out, nullptr, out, nullptr, nullptr, E_, E_, 0);

    // 4) temporal-H: ot = o_th
    flash_tf32<1><<<dim3(1, NH_, B_ * 28), 256, FSMEM>>>(qkv, qt, ot, 1, 28, 0);

    // 5) temporal-W: ot += o_tw
    flash_tf32<1><<<dim3(1, NH_, B_ * 28), 256, FSMEM>>>(qkv, qt, ot, 28, 1, 1);

    // 6) out = xs + alpha * (ot @ w_to^T + b_to)
    gemm_tf32<<<dim3(4, 98), 256, GSMEM>>>(
        ot, gw3, b_to, nullptr, out, nullptr, alpha, E_, E_, 2);
}

// round 7
// speedup vs baseline: 2.3476x; 1.8673x over previous
#include <cuda_runtime.h>
#include <cuda_fp16.h>
#include <math.h>

#define B_    4
#define E_    512
#define NH_   8
#define HWP_  784
#define NN_   3136
#define ROWS_ 12544
#define SCALE_ 0.125f
#define KP_   256          // GEMM K in half2 pairs (512/2)

// fp16 scratch. q/k of qkv, qt, sp, ot: sigma-permuted half2 pairs per 8-pair
// group (stored pos sigma(p)=2(p&3)+(p>>2)); v part of qkv: natural (ldmatrix).
__device__ __half2 g_qkv[ROWS_ * 768];
__device__ __half2 g_sp [ROWS_ * 256];
__device__ __half2 g_qt [ROWS_ * 256];
__device__ __half2 g_ot [ROWS_ * 256];
__device__ __half2 g_x  [ROWS_ * 256];
__device__ __half2 g_w1 [2048 * 256];
__device__ __half2 g_w2 [512 * 256];
__device__ __half2 g_w3 [512 * 256];

__device__ __forceinline__ unsigned h2u(float a, float b) {
    __half2 h = __floats2half2_rn(a, b);
    return *(unsigned*)&h;
}
__device__ __forceinline__ void mma16(float4& d, const unsigned* a, unsigned b0, unsigned b1) {
    asm volatile("mma.sync.aligned.m16n8k16.row.col.f32.f16.f16.f32 "
        "{%0,%1,%2,%3},{%4,%5,%6,%7},{%8,%9},{%0,%1,%2,%3};"
        : "+f"(d.x), "+f"(d.y), "+f"(d.z), "+f"(d.w)
        : "r"(a[0]), "r"(a[1]), "r"(a[2]), "r"(a[3]), "r"(b0), "r"(b1));
}
__device__ __forceinline__ void ldmx2t(unsigned& b0, unsigned& b1, unsigned addr) {
    asm volatile("ldmatrix.sync.aligned.m8n8.x2.trans.shared.b16 {%0,%1}, [%2];"
        : "=r"(b0), "=r"(b1) : "r"(addr));
}
__device__ __forceinline__ void cpa16(void* sdst, const void* gsrc) {
    unsigned s = (unsigned)__cvta_generic_to_shared(sdst);
    asm volatile("cp.async.ca.shared.global [%0], [%1], 16;" :: "r"(s), "l"(gsrc));
}
#define CP_COMMIT() asm volatile("cp.async.commit_group;" ::: "memory")
#define CP_WAIT(n)  asm volatile("cp.async.wait_group %0;" :: "n"(n) : "memory")

// ---------------------------------------------------------------------------
// Prep: fp16-round + sigma-permute (16 floats = one 8-pair group per thread).
// ---------------------------------------------------------------------------
#define NXG  401408
#define NWIG 49152
#define NWG  16384
#define NPG  (NXG + NWIG + 4 * NWG)    // 499712 = 1952*256

__global__ __launch_bounds__(256)
void prep_h(const float4* __restrict__ x,  const float4* __restrict__ w_in,
            const float4* __restrict__ w_t, const float4* __restrict__ w_out,
            const float4* __restrict__ w_to,
            uint4* __restrict__ gx, uint4* __restrict__ gw1,
            uint4* __restrict__ gw2, uint4* __restrict__ gw3)
{
    long i = (long)blockIdx.x * 256 + threadIdx.x;
    const float4* s; uint4* d;
    if      (i < NXG)                 { s = x + 4*i;                        d = gx + 2*i; }
    else if (i < NXG + NWIG)          { long j = i - NXG;                   s = w_in + 4*j;  d = gw1 + 2*j; }
    else if (i < NXG + NWIG + NWG)    { long j = i - NXG - NWIG;            s = w_t + 4*j;   d = gw1 + 2*(NWIG + j); }
    else if (i < NXG + NWIG + 2*NWG)  { long j = i - NXG - NWIG - NWG;      s = w_out + 4*j; d = gw2 + 2*j; }
    else if (i < NPG)                 { long j = i - NXG - NWIG - 2*NWG;    s = w_to + 4*j;  d = gw3 + 2*j; }
    else return;
    float4 f0 = s[0], f1 = s[1], f2 = s[2], f3 = s[3];
    unsigned h0 = h2u(f0.x, f0.y), h1 = h2u(f0.z, f0.w);
    unsigned h2 = h2u(f1.x, f1.y), h3 = h2u(f1.z, f1.w);
    unsigned h4 = h2u(f2.x, f2.y), h5 = h2u(f2.z, f2.w);
    unsigned h6 = h2u(f3.x, f3.y), h7 = h2u(f3.z, f3.w);
    d[0] = make_uint4(h0, h4, h1, h5);     // sigma: pos j holds pair sigma^-1(j)
    d[1] = make_uint4(h2, h6, h3, h7);
}

// ---------------------------------------------------------------------------
// fp16 GEMM: 4-stage cp.async, BK=32 k-values (16 pairs), pitch 24 words.
// C = A[M,512] @ W[N,512]^T + bias. A/W sigma-permuted half2.
// mode 0: Cf = acc+bias (f32)
// mode 2: Cf = Cf + alpha[n]*(acc+bias) (f32)
// mode 3: merged qkv+qt: col<512 q(*SCALE_,sigma) | <1024 k(sigma) |
//         <1536 v(natural) -> Ch ; >=1536 qt(*SCALE_,sigma) -> C2
// ---------------------------------------------------------------------------
#define GP    24
#define GSTG  (128 * GP)
#define GSMEM (8 * GSTG * 4)

__global__ __launch_bounds__(256, 2)
void gemm_h(const __half2* __restrict__ A, const __half2* __restrict__ W,
            const float* __restrict__ bias, const float* __restrict__ bias2,
            float* __restrict__ Cf, __half2* __restrict__ Ch, __half2* __restrict__ C2,
            const float* __restrict__ alpha, int N, int mode)
{
    extern __shared__ unsigned gsm[];
    unsigned* sA = gsm;
    unsigned* sB = gsm + 4 * GSTG;
    const int bm = blockIdx.y * 128, bn = blockIdx.x * 128;
    const int tid  = threadIdx.x;
    const int warp = tid >> 5, lane = tid & 31;
    const int wm = (warp >> 1) * 32, wn = (warp & 1) * 64;
    const int row = lane >> 2, t4 = lane & 3;

    auto stage = [&](int s, int k0p) {
        unsigned* dA = sA + s * GSTG;
        unsigned* dB = sB + s * GSTG;
#pragma unroll
        for (int i = 0; i < 2; i++) {
            int idx = tid * 2 + i;
            int r = idx >> 2, c4 = (idx & 3) << 2;
            cpa16(dA + r * GP + c4, A + (size_t)(bm + r) * KP_ + k0p + c4);
            cpa16(dB + r * GP + c4, W + (size_t)(bn + r) * KP_ + k0p + c4);
        }
    };

    float4 acc[2][8];
#pragma unroll
    for (int i = 0; i < 2; i++)
#pragma unroll
        for (int j = 0; j < 8; j++) acc[i][j] = make_float4(0.f, 0.f, 0.f, 0.f);

    const int nsl = KP_ / 16;   // 16 slabs of 16 pairs
    stage(0, 0);  CP_COMMIT();
    stage(1, 16); CP_COMMIT();

    for (int i = 0; i < nsl; i++) {
        if (i + 2 < nsl) stage((i + 2) & 3, (i + 2) * 16);
        CP_COMMIT();
        CP_WAIT(2);
        __syncthreads();

        const unsigned* cA = sA + (i & 3) * GSTG;
        const unsigned* cB = sB + (i & 3) * GSTG;
#pragma unroll
        for (int ks = 0; ks < 16; ks += 8) {
            unsigned a[2][4];
#pragma unroll
            for (int mt = 0; mt < 2; mt++) {
                const unsigned* p = cA + (wm + mt * 16 + row) * GP + ks + 2 * t4;
                uint2 u0 = *(const uint2*)p;
                uint2 u1 = *(const uint2*)(p + 8 * GP);
                a[mt][0] = u0.x; a[mt][1] = u1.x; a[mt][2] = u0.y; a[mt][3] = u1.y;
            }
#pragma unroll
            for (int nt = 0; nt < 8; nt++) {
                uint2 ub = *(const uint2*)(cB + (wn + nt * 8 + row) * GP + ks + 2 * t4);
                mma16(acc[0][nt], a[0], ub.x, ub.y);
                mma16(acc[1][nt], a[1], ub.x, ub.y);
            }
        }
    }

#pragma unroll
    for (int mt = 0; mt < 2; mt++) {
        int rg = bm + wm + mt * 16 + row;
#pragma unroll
        for (int nt = 0; nt < 8; nt++) {
            int cg = bn + wn + nt * 8 + 2 * t4;
            float v0 = acc[mt][nt].x, v1 = acc[mt][nt].y;
            float v2 = acc[mt][nt].z, v3 = acc[mt][nt].w;
            if (mode == 3) {
                float bb0, bb1, sc;
                __half2* dst; int off, dstr; bool natural;
                if (cg < 1536) {
                    bb0 = bias[cg]; bb1 = bias[cg + 1];
                    sc = (cg < 512) ? SCALE_ : 1.f;
                    dst = Ch; off = 0; dstr = 768; natural = (cg >= 1024);
                } else {
                    bb0 = bias2[cg - 1536]; bb1 = bias2[cg - 1535];
                    sc = SCALE_;
                    dst = C2; off = 1536; dstr = 256; natural = false;
                }
                v0 = (v0 + bb0) * sc; v1 = (v1 + bb1) * sc;
                v2 = (v2 + bb0) * sc; v3 = (v3 + bb1) * sc;
                int pd = (cg - off) >> 1;
                int pos = natural ? pd : ((pd & ~7) + 2 * (pd & 3) + ((pd >> 2) & 1));
                dst[(size_t)rg * dstr + pos]       = __floats2half2_rn(v0, v1);
                dst[(size_t)(rg + 8) * dstr + pos] = __floats2half2_rn(v2, v3);
            } else {
                float bb0 = bias[cg], bb1 = bias[cg + 1];
                v0 += bb0; v1 += bb1; v2 += bb0; v3 += bb1;
                size_t i0 = (size_t)rg * N + cg;
                size_t i1 = (size_t)(rg + 8) * N + cg;
                if (mode == 2) {
                    float a0 = alpha[cg], a1 = alpha[cg + 1];
                    float2 o0 = *(const float2*)(Cf + i0);
                    float2 o1 = *(const float2*)(Cf + i1);
                    v0 = o0.x + a0 * v0; v1 = o0.y + a1 * v1;
                    v2 = o1.x + a0 * v2; v3 = o1.y + a1 * v3;
                }
                *(float2*)(Cf + i0) = make_float2(v0, v1);
                *(float2*)(Cf + i1) = make_float2(v2, v3);
            }
        }
    }
}

// ---------------------------------------------------------------------------
// fp16 flash attention. 256 thr = 8 warps, BQ=128, key tiles 64, D=64.
// Q/K sigma-paired (uint2 frags), V natural (ldmatrix.x2.trans), P sigma-paired.
// smem: Qs/Ps[128][40] | Kb[2][64][40] | Vb[2][64][36] = 59392 B
// ---------------------------------------------------------------------------
#define QP 40
#define VP 36
#define KTILE (64 * QP)
#define VTILE (64 * VP)
#define FSMEM ((128 * QP + 2 * KTILE + 2 * VTILE) * 4)

template<int TMP>
__global__ __launch_bounds__(256, 2)
void flash_h(const __half2* __restrict__ qkv, const __half2* __restrict__ qsrc,
             int qstride, __half2* __restrict__ out, int fs, int vs, int accum)
{
    extern __shared__ unsigned sm[];
    unsigned* Qs = sm;                  // reused per-warp as P
    unsigned* Kb = sm + 128 * QP;
    unsigned* Vb = Kb + 2 * KTILE;

    const int tid  = threadIdx.x;
    const int warp = tid >> 5, lane = tid & 31;
    const int row  = lane >> 2, t4 = lane & 3;
    const int head = blockIdx.y;
    const int q0   = blockIdx.x * 128;

    int b = 0, fixed = 0, bt = 0;
    if (TMP) { b = blockIdx.z / 28; fixed = blockIdx.z % 28; }
    else     { bt = blockIdx.z; }

    const int Lq    = TMP ? 112 : HWP_;
    const int lastr = min(q0 + 127, Lq - 1);
    const int kmaxb = TMP ? (lastr / 28 + 1) * 28 : HWP_;

    auto stageKV = [&](int buf, int ktt) {
        unsigned* Kd = Kb + buf * KTILE;
        unsigned* Vd = Vb + buf * VTILE;
        for (int f = tid; f < 512; f += 256) {
            int j = f >> 3, c = (f & 7) << 2;
            int kk = min(ktt + j, kmaxb - 1);
            size_t base;
            if (TMP) {
                int nk = (kk / 28) * HWP_ + fixed * fs + (kk % 28) * vs;
                base = (size_t)(b * NN_ + nk) * 768 + head * 32 + c;
            } else {
                base = (size_t)(bt * HWP_ + kk) * 768 + head * 32 + c;
            }
            cpa16(Kd + j * QP + c, qkv + base + 256);
            cpa16(Vd + j * VP + c, qkv + base + 512);
        }
    };

    for (int f = tid; f < 1024; f += 256) {
        int r = f >> 3, c = (f & 7) << 2;
        int rq = min(q0 + r, Lq - 1);
        const __half2* src;
        if (TMP) {
            int nq = (rq / 28) * HWP_ + fixed * fs + (rq % 28) * vs;
            src = qsrc + (size_t)(b * NN_ + nq) * qstride + head * 32 + c;
        } else {
            src = qsrc + (size_t)(bt * HWP_ + rq) * qstride + head * 32 + c;
        }
        cpa16(Qs + r * QP + c, src);
    }
    stageKV(0, 0);
    CP_COMMIT();

    const int r0 = q0 + warp * 16 + row;
    const int lim0 = TMP ? min((r0 / 28 + 1) * 28, 112) : HWP_;
    const int lim1 = TMP ? min(((r0 + 8) / 28 + 1) * 28, 112) : HWP_;
    const int warpLim = TMP ? min(((q0 + warp * 16 + 15) / 28 + 1) * 28, 112) : HWP_;

    unsigned q[4][4];
    float m0 = -1e30f, m1 = -1e30f, l0 = 0.f, l1 = 0.f;
    float4 o[8];
#pragma unroll
    for (int nt = 0; nt < 8; nt++) o[nt] = make_float4(0.f, 0.f, 0.f, 0.f);

    unsigned* Ps = Qs + warp * 16 * QP;

    for (int kt = 0, cur = 0; kt < kmaxb; kt += 64, cur ^= 1) {
        if (kt + 64 < kmaxb) stageKV(cur ^ 1, kt + 64);
        CP_COMMIT();
        CP_WAIT(1);
        __syncthreads();

        unsigned* Ks = Kb + cur * KTILE;
        unsigned* Vs = Vb + cur * VTILE;

        if (kt == 0) {
            int rm = warp * 16 + row;
#pragma unroll
            for (int kd = 0; kd < 4; kd++) {
                uint2 u0 = *(const uint2*)(Qs + rm * QP + kd * 8 + 2 * t4);
                uint2 u1 = *(const uint2*)(Qs + (rm + 8) * QP + kd * 8 + 2 * t4);
                q[kd][0] = u0.x; q[kd][1] = u1.x; q[kd][2] = u0.y; q[kd][3] = u1.y;
            }
        }

        if (kt < warpLim) {
            // ---- S = Q @ K^T ----
            float4 s[8];
#pragma unroll
            for (int nt = 0; nt < 8; nt++) s[nt] = make_float4(0.f, 0.f, 0.f, 0.f);
#pragma unroll
            for (int kd = 0; kd < 4; kd++) {
#pragma unroll
                for (int nt = 0; nt < 8; nt++) {
                    uint2 ub = *(const uint2*)(Ks + (nt * 8 + row) * QP + kd * 8 + 2 * t4);
                    mma16(s[nt], q[kd], ub.x, ub.y);
                }
            }

            if (TMP || kt + 64 > HWP_) {
                int cb = kt + 2 * t4;
#pragma unroll
                for (int nt = 0; nt < 8; nt++) {
                    int c0 = cb + 8 * nt;
                    if (c0     >= lim0) s[nt].x = -1e30f;
                    if (c0 + 1 >= lim0) s[nt].y = -1e30f;
                    if (c0     >= lim1) s[nt].z = -1e30f;
                    if (c0 + 1 >= lim1) s[nt].w = -1e30f;
                }
            }
            float mx0 = -1e30f, mx1 = -1e30f;
#pragma unroll
            for (int nt = 0; nt < 8; nt++) {
                mx0 = fmaxf(mx0, fmaxf(s[nt].x, s[nt].y));
                mx1 = fmaxf(mx1, fmaxf(s[nt].z, s[nt].w));
            }
            mx0 = fmaxf(mx0, __shfl_xor_sync(0xffffffffu, mx0, 1));
            mx0 = fmaxf(mx0, __shfl_xor_sync(0xffffffffu, mx0, 2));
            mx1 = fmaxf(mx1, __shfl_xor_sync(0xffffffffu, mx1, 1));
            mx1 = fmaxf(mx1, __shfl_xor_sync(0xffffffffu, mx1, 2));
            float mn0 = fmaxf(m0, mx0), mn1 = fmaxf(m1, mx1);
            float corr0 = __expf(m0 - mn0), corr1 = __expf(m1 - mn1);
            float ps0 = 0.f, ps1 = 0.f;
#pragma unroll
            for (int nt = 0; nt < 8; nt++) {
                s[nt].x = __expf(s[nt].x - mn0); ps0 += s[nt].x;
                s[nt].y = __expf(s[nt].y - mn0); ps0 += s[nt].y;
                s[nt].z = __expf(s[nt].z - mn1); ps1 += s[nt].z;
                s[nt].w = __expf(s[nt].w - mn1); ps1 += s[nt].w;
            }
            ps0 += __shfl_xor_sync(0xffffffffu, ps0, 1);
            ps0 += __shfl_xor_sync(0xffffffffu, ps0, 2);
            ps1 += __shfl_xor_sync(0xffffffffu, ps1, 1);
            ps1 += __shfl_xor_sync(0xffffffffu, ps1, 2);
            l0 = l0 * corr0 + ps0; l1 = l1 * corr1 + ps1;
            m0 = mn0; m1 = mn1;
#pragma unroll
            for (int nt = 0; nt < 8; nt++) {
                o[nt].x *= corr0; o[nt].y *= corr0;
                o[nt].z *= corr1; o[nt].w *= corr1;
            }

            // ---- store P (fp16 pairs, sigma positions; warp-private) ----
#pragma unroll
            for (int nt = 0; nt < 8; nt++) {
                int pos = 8 * (nt >> 1) + 2 * t4 + (nt & 1);
                Ps[row * QP + pos]       = h2u(s[nt].x, s[nt].y);
                Ps[(row + 8) * QP + pos] = h2u(s[nt].z, s[nt].w);
            }
            __syncwarp();

            // ---- O += P @ V (V via ldmatrix.x2.trans) ----
            unsigned vsb = (unsigned)__cvta_generic_to_shared(Vs);
#pragma unroll
            for (int kk = 0; kk < 4; kk++) {
                uint2 u0 = *(const uint2*)(Ps + row * QP + kk * 8 + 2 * t4);
                uint2 u1 = *(const uint2*)(Ps + (row + 8) * QP + kk * 8 + 2 * t4);
                unsigned a[4] = {u0.x, u1.x, u0.y, u1.y};
                unsigned rowaddr = vsb + (unsigned)((kk * 16 + (lane & 15)) * VP) * 4u;
#pragma unroll
                for (int nt = 0; nt < 8; nt++) {
                    unsigned b0, b1;
                    ldmx2t(b0, b1, rowaddr + nt * 16);
                    mma16(o[nt], a, b0, b1);
                }
            }
            __syncwarp();
        }
        __syncthreads();
    }

    // ---- epilogue: normalize, fp16-round to sigma-paired layout ----
    float inv0 = 1.f / l0, inv1 = 1.f / l1;
#pragma unroll
    for (int nt = 0; nt < 8; nt++) {
        int pos = 8 * (nt >> 1) + 2 * t4 + (nt & 1);
        if (r0 < Lq) {
            size_t ob;
            if (TMP) {
                int nq = (r0 / 28) * HWP_ + fixed * fs + (r0 % 28) * vs;
                ob = (size_t)(b * NN_ + nq) * 256 + head * 32 + pos;
            } else {
                ob = (size_t)(bt * HWP_ + r0) * 256 + head * 32 + pos;
            }
            float rx = o[nt].x * inv0, ry = o[nt].y * inv0;
            if (TMP && accum) {
                __half2 old = out[ob];
                rx += __low2float(old); ry += __high2float(old);
            }
            out[ob] = __floats2half2_rn(rx, ry);
        }
        if (r0 + 8 < Lq) {
            int r1 = r0 + 8;
            size_t ob;
            if (TMP) {
                int nq = (r1 / 28) * HWP_ + fixed * fs + (r1 % 28) * vs;
                ob = (size_t)(b * NN_ + nq) * 256 + head * 32 + pos;
            } else {
                ob = (size_t)(bt * HWP_ + r1) * 256 + head * 32 + pos;
            }
            float rx = o[nt].z * inv1, ry = o[nt].w * inv1;
            if (TMP && accum) {
                __half2 old = out[ob];
                rx += __low2float(old); ry += __high2float(old);
            }
            out[ob] = __floats2half2_rn(rx, ry);
        }
    }
}

// ---------------------------------------------------------------------------
extern "C" void kernel_launch(void* const* d_in, const int* in_sizes, int n_in,
                              void* d_out, int out_size)
{
    const float* x      = (const float*)d_in[0];
    const float* w_in   = (const float*)d_in[1];
    const float* b_in   = (const float*)d_in[2];
    const float* w_out  = (const float*)d_in[3];
    const float* b_out  = (const float*)d_in[4];
    const float* w_t    = (const float*)d_in[5];
    const float* b_t    = (const float*)d_in[6];
    const float* w_to   = (const float*)d_in[7];
    const float* b_to   = (const float*)d_in[8];
    const float* alpha  = (const float*)d_in[9];
    float* out = (float*)d_out;

    __half2 *qkv, *sp, *qt, *ot, *gx, *gw1, *gw2, *gw3;
    cudaGetSymbolAddress((void**)&qkv, g_qkv);
    cudaGetSymbolAddress((void**)&sp,  g_sp);
    cudaGetSymbolAddress((void**)&qt,  g_qt);
    cudaGetSymbolAddress((void**)&ot,  g_ot);
    cudaGetSymbolAddress((void**)&gx,  g_x);
    cudaGetSymbolAddress((void**)&gw1, g_w1);
    cudaGetSymbolAddress((void**)&gw2, g_w2);
    cudaGetSymbolAddress((void**)&gw3, g_w3);

    cudaFuncSetAttribute(gemm_h,    cudaFuncAttributeMaxDynamicSharedMemorySize, GSMEM);
    cudaFuncSetAttribute(flash_h<0>, cudaFuncAttributeMaxDynamicSharedMemorySize, FSMEM);
    cudaFuncSetAttribute(flash_h<1>, cudaFuncAttributeMaxDynamicSharedMemorySize, FSMEM);

    // 0) fp16-round + sigma-permute x + weights
    prep_h<<<NPG / 256, 256>>>(
        (const float4*)x, (const float4*)w_in, (const float4*)w_t,
        (const float4*)w_out, (const float4*)w_to,
        (uint4*)gx, (uint4*)gw1, (uint4*)gw2, (uint4*)gw3);

    // 1) merged qkv + qt projection (N=2048)
    gemm_h<<<dim3(16, 98), 256, GSMEM>>>(
        gx, gw1, b_in, b_t, nullptr, qkv, qt, nullptr, 2048, 3);

    // 2) spatial attention -> sp
    flash_h<0><<<dim3(7, NH_, 16), 256, FSMEM>>>(qkv, qkv, 768, sp, 0, 0, 0);

    // 3) xs = sp @ w_out^T + b_out -> out (f32)
    gemm_h<<<dim3(4, 98), 256, GSMEM>>>(
        sp, gw2, b_out, nullptr, out, nullptr, nullptr, nullptr, 512, 0);

    // 4) temporal-H: ot = o_th
    flash_h<1><<<dim3(1, NH_, B_ * 28), 256, FSMEM>>>(qkv, qt, 256, ot, 1, 28, 0);

    // 5) temporal-W: ot += o_tw
    flash_h<1><<<dim3(1, NH_, B_ * 28), 256, FSMEM>>>(qkv, qt, 256, ot, 28, 1, 1);

    // 6) out = xs + alpha * (ot @ w_to^T + b_to)
    gemm_h<<<dim3(4, 98), 256, GSMEM>>>(
        ot, gw3, b_to, nullptr, out, nullptr, nullptr, alpha, 512, 2);
}

// round 9
// speedup vs baseline: 2.4957x; 1.0631x over previous
#include <cuda_runtime.h>
#include <cuda_fp16.h>
#include <math.h>

#define B_    4
#define E_    512
#define NH_   8
#define HWP_  784
#define NN_   3136
#define ROWS_ 12544
#define SCALE_ 0.125f

// fp16 scratch. q/k of qkv, qt, sp, ot: sigma-permuted half2 pairs per 8-pair
// group (stored pos sigma(p)=2(p&3)+(p>>2)); v part of qkv: natural (ldmatrix).
__device__ __half2 g_qkv[ROWS_ * 768];
__device__ __half2 g_sp [ROWS_ * 256];
__device__ __half2 g_qt [ROWS_ * 256];
__device__ __half2 g_ot [ROWS_ * 256];
__device__ __half2 g_x  [ROWS_ * 256];
__device__ __half2 g_w1 [2048 * 256];
__device__ __half2 g_w2 [512 * 256];
__device__ __half2 g_w3 [512 * 256];

__device__ __forceinline__ unsigned h2u(float a, float b) {
    __half2 h = __floats2half2_rn(a, b);
    return *(unsigned*)&h;
}
__device__ __forceinline__ void mma16(float4& d, const unsigned* a, unsigned b0, unsigned b1) {
    asm volatile("mma.sync.aligned.m16n8k16.row.col.f32.f16.f16.f32 "
        "{%0,%1,%2,%3},{%4,%5,%6,%7},{%8,%9},{%0,%1,%2,%3};"
        : "+f"(d.x), "+f"(d.y), "+f"(d.z), "+f"(d.w)
        : "r"(a[0]), "r"(a[1]), "r"(a[2]), "r"(a[3]), "r"(b0), "r"(b1));
}
__device__ __forceinline__ void ldmx4(unsigned& r0, unsigned& r1, unsigned& r2,
                                      unsigned& r3, unsigned addr) {
    asm volatile("ldmatrix.sync.aligned.m8n8.x4.shared.b16 {%0,%1,%2,%3}, [%4];"
        : "=r"(r0), "=r"(r1), "=r"(r2), "=r"(r3) : "r"(addr));
}
__device__ __forceinline__ void ldmx2t(unsigned& b0, unsigned& b1, unsigned addr) {
    asm volatile("ldmatrix.sync.aligned.m8n8.x2.trans.shared.b16 {%0,%1}, [%2];"
        : "=r"(b0), "=r"(b1) : "r"(addr));
}
__device__ __forceinline__ void cpa16(void* sdst, const void* gsrc) {
    unsigned s = (unsigned)__cvta_generic_to_shared(sdst);
    asm volatile("cp.async.ca.shared.global [%0], [%1], 16;" :: "r"(s), "l"(gsrc));
}
__device__ __forceinline__ void cpa16s(unsigned sdst, const void* gsrc) {
    asm volatile("cp.async.ca.shared.global [%0], [%1], 16;" :: "r"(sdst), "l"(gsrc));
}
#define CP_COMMIT() asm volatile("cp.async.commit_group;" ::: "memory")
#define CP_WAIT(n)  asm volatile("cp.async.wait_group %0;" :: "n"(n) : "memory")

// ---------------------------------------------------------------------------
// Prep: fp16-round + sigma-permute (16 floats = one 8-pair group per thread).
// ---------------------------------------------------------------------------
#define NXG  401408
#define NWIG 49152
#define NWG  16384
#define NPG  (NXG + NWIG + 4 * NWG)

__global__ __launch_bounds__(256)
void prep_h(const float4* __restrict__ x,  const float4* __restrict__ w_in,
            const float4* __restrict__ w_t, const float4* __restrict__ w_out,
            const float4* __restrict__ w_to,
            uint4* __restrict__ gx, uint4* __restrict__ gw1,
            uint4* __restrict__ gw2, uint4* __restrict__ gw3)
{
    long i = (long)blockIdx.x * 256 + threadIdx.x;
    const float4* s; uint4* d;
    if      (i < NXG)                 { s = x + 4*i;                        d = gx + 2*i; }
    else if (i < NXG + NWIG)          { long j = i - NXG;                   s = w_in + 4*j;  d = gw1 + 2*j; }
    else if (i < NXG + NWIG + NWG)    { long j = i - NXG - NWIG;            s = w_t + 4*j;   d = gw1 + 2*(NWIG + j); }
    else if (i < NXG + NWIG + 2*NWG)  { long j = i - NXG - NWIG - NWG;      s = w_out + 4*j; d = gw2 + 2*j; }
    else if (i < NPG)                 { long j = i - NXG - NWIG - 2*NWG;    s = w_to + 4*j;  d = gw3 + 2*j; }
    else return;
    float4 f0 = s[0], f1 = s[1], f2 = s[2], f3 = s[3];
    unsigned h0 = h2u(f0.x, f0.y), h1 = h2u(f0.z, f0.w);
    unsigned h2 = h2u(f1.x, f1.y), h3 = h2u(f1.z, f1.w);
    unsigned h4 = h2u(f2.x, f2.y), h5 = h2u(f2.z, f2.w);
    unsigned h6 = h2u(f3.x, f3.y), h7 = h2u(f3.z, f3.w);
    d[0] = make_uint4(h0, h4, h1, h5);
    d[1] = make_uint4(h2, h6, h3, h7);
}

// ---------------------------------------------------------------------------
// fp16 GEMM via mma.sync + ldmatrix.x4. 4-stage cp.async, BK=32 halfs,
// smem row pitch 80 B (conflict-free for ldmatrix: 80r mod 128 all distinct).
// C = A[M,512] @ W[N,512]^T + bias. A/W sigma-paired fp16.
// mode 0: Cf = acc+bias (f32)
// mode 2: Cf = Cf + alpha[n]*(acc+bias) (f32)
// mode 3: merged qkv+qt: col<512 q(*SCALE_,sigma) | <1024 k(sigma) |
//         <1536 v(natural) -> Ch ; >=1536 qt(*SCALE_,sigma) -> C2
// ---------------------------------------------------------------------------
#define STGB  10240u                 // 128 rows * 80 B, per matrix per stage
#define GSMEM (8 * 10240)            // 4 stages x (A+B) = 81920 B

__global__ __launch_bounds__(256, 2)
void gemm_h(const __half* __restrict__ A, const __half* __restrict__ W,
            const float* __restrict__ bias, const float* __restrict__ bias2,
            float* __restrict__ Cf, __half2* __restrict__ Ch, __half2* __restrict__ C2,
            const float* __restrict__ alpha, int N, int mode)
{
    extern __shared__ __half gsmh[];
    const unsigned sbase = (unsigned)__cvta_generic_to_shared(gsmh);
    const int bm = blockIdx.y * 128, bn = blockIdx.x * 128;
    const int tid  = threadIdx.x;
    const int warp = tid >> 5, lane = tid & 31;
    const int wm = (warp >> 1) * 32, wn = (warp & 1) * 64;
    const int row = lane >> 2, t4 = lane & 3;

    // staging: thread owns one row, two adjacent 16B slots, per matrix
    const int srow  = tid >> 1;
    const int sslot = (tid & 1) * 2;
    const __half* gA = A + (size_t)(bm + srow) * 512 + sslot * 8;
    const __half* gW = W + (size_t)(bn + srow) * 512 + sslot * 8;
    const unsigned soff = (unsigned)srow * 80u + (unsigned)sslot * 16u;

    auto stage = [&](int s, int k0) {      // k0 in halfs
        unsigned d = sbase + (unsigned)s * STGB + soff;
        cpa16s(d,      gA + k0);
        cpa16s(d + 16, gA + k0 + 8);
        unsigned d2 = d + 4 * STGB;
        cpa16s(d2,      gW + k0);
        cpa16s(d2 + 16, gW + k0 + 8);
    };

    // fragment base offsets (ldmatrix addressing)
    const unsigned aoff = (unsigned)(wm + (lane & 15)) * 80u + (unsigned)(lane >> 4) * 16u;
    const unsigned boff = 4 * STGB + (unsigned)(wn + (lane & 15)) * 80u + (unsigned)(lane >> 4) * 16u;

    float4 acc[2][8];
#pragma unroll
    for (int i = 0; i < 2; i++)
#pragma unroll
        for (int j = 0; j < 8; j++) acc[i][j] = make_float4(0.f, 0.f, 0.f, 0.f);

    stage(0, 0);  CP_COMMIT();
    stage(1, 32); CP_COMMIT();

    for (int i = 0; i < 16; i++) {         // 16 slabs x 32 halfs = K 512
        if (i + 2 < 16) stage((i + 2) & 3, (i + 2) * 32);
        CP_COMMIT();
        CP_WAIT(2);
        __syncthreads();

        unsigned ab = sbase + (unsigned)(i & 3) * STGB + aoff;
        unsigned bb = sbase + (unsigned)(i & 3) * STGB + boff;
#pragma unroll
        for (int ks = 0; ks < 2; ks++) {   // two k16 fragments per slab
            unsigned a[2][4];
            ldmx4(a[0][0], a[0][1], a[0][2], a[0][3], ab + ks * 32);
            ldmx4(a[1][0], a[1][1], a[1][2], a[1][3], ab + 1280 + ks * 32);
#pragma unroll
            for (int g = 0; g < 4; g++) {
                unsigned r0, r1, r2, r3;
                ldmx4(r0, r1, r2, r3, bb + g * 1280 + ks * 32);
                mma16(acc[0][2*g],   a[0], r0, r2);
                mma16(acc[0][2*g+1], a[0], r1, r3);
                mma16(acc[1][2*g],   a[1], r0, r2);
                mma16(acc[1][2*g+1], a[1], r1, r3);
            }
        }
    }

#pragma unroll
    for (int mt = 0; mt < 2; mt++) {
        int rg = bm + wm + mt * 16 + row;
#pragma unroll
        for (int nt = 0; nt < 8; nt++) {
            int cg = bn + wn + nt * 8 + 2 * t4;
            float v0 = acc[mt][nt].x, v1 = acc[mt][nt].y;
            float v2 = acc[mt][nt].z, v3 = acc[mt][nt].w;
            if (mode == 3) {
                float bb0, bb1, sc;
                __half2* dst; int off, dstr; bool natural;
                if (cg < 1536) {
                    bb0 = bias[cg]; bb1 = bias[cg + 1];
                    sc = (cg < 512) ? SCALE_ : 1.f;
                    dst = Ch; off = 0; dstr = 768; natural = (cg >= 1024);
                } else {
                    bb0 = bias2[cg - 1536]; bb1 = bias2[cg - 1535];
                    sc = SCALE_;
                    dst = C2; off = 1536; dstr = 256; natural = false;
                }
                v0 = (v0 + bb0) * sc; v1 = (v1 + bb1) * sc;
                v2 = (v2 + bb0) * sc; v3 = (v3 + bb1) * sc;
                int pd = (cg - off) >> 1;
                int pos = natural ? pd : ((pd & ~7) + 2 * (pd & 3) + ((pd >> 2) & 1));
                dst[(size_t)rg * dstr + pos]       = __floats2half2_rn(v0, v1);
                dst[(size_t)(rg + 8) * dstr + pos] = __floats2half2_rn(v2, v3);
            } else {
                float bb0 = bias[cg], bb1 = bias[cg + 1];
                v0 += bb0; v1 += bb1; v2 += bb0; v3 += bb1;
                size_t i0 = (size_t)rg * N + cg;
                size_t i1 = (size_t)(rg + 8) * N + cg;
                if (mode == 2) {
                    float a0 = alpha[cg], a1 = alpha[cg + 1];
                    float2 o0 = *(const float2*)(Cf + i0);
                    float2 o1 = *(const float2*)(Cf + i1);
                    v0 = o0.x + a0 * v0; v1 = o0.y + a1 * v1;
                    v2 = o1.x + a0 * v2; v3 = o1.y + a1 * v3;
                }
                *(float2*)(Cf + i0) = make_float2(v0, v1);
                *(float2*)(Cf + i1) = make_float2(v2, v3);
            }
        }
    }
}

// ---------------------------------------------------------------------------
// fp16 flash attention. 256 thr = 8 warps, BQ=128, key tiles 64, D=64.
// Q canonical frags (LDS.32 once); K frags via ldmatrix.x4 (pitch 144 B,
// conflict-free); V natural via ldmatrix.x2.trans; P sigma-paired (round-7
// proven path). smem: Qs/Ps[128][40] | Kb[2][64][36] | Vb[2][64][36]
// ---------------------------------------------------------------------------
#define QP 40
#define KP 36
#define VP 36
#define KTILE (64 * KP)
#define VTILE (64 * VP)
#define FSMEM ((128 * QP + 2 * KTILE + 2 * VTILE) * 4)

template<int TMP>
__global__ __launch_bounds__(256, 2)
void flash_h(const __half2* __restrict__ qkv, const __half2* __restrict__ qsrc,
             int qstride, __half2* __restrict__ out, int fs, int vs, int accum)
{
    extern __shared__ unsigned sm[];
    unsigned* Qs = sm;
    unsigned* Kb = sm + 128 * QP;
    unsigned* Vb = Kb + 2 * KTILE;

    const int tid  = threadIdx.x;
    const int warp = tid >> 5, lane = tid & 31;
    const int row  = lane >> 2, t4 = lane & 3;
    const int head = blockIdx.y;
    const int q0   = blockIdx.x * 128;

    int b = 0, fixed = 0, bt = 0;
    if (TMP) { b = blockIdx.z / 28; fixed = blockIdx.z % 28; }
    else     { bt = blockIdx.z; }

    const int Lq    = TMP ? 112 : HWP_;
    const int lastr = min(q0 + 127, Lq - 1);
    const int kmaxb = TMP ? (lastr / 28 + 1) * 28 : HWP_;

    auto stageKV = [&](int buf, int ktt) {
        unsigned* Kd = Kb + buf * KTILE;
        unsigned* Vd = Vb + buf * VTILE;
        for (int f = tid; f < 512; f += 256) {
            int j = f >> 3, c = (f & 7) << 2;
            int kk = min(ktt + j, kmaxb - 1);
            size_t base;
            if (TMP) {
                int nk = (kk / 28) * HWP_ + fixed * fs + (kk % 28) * vs;
                base = (size_t)(b * NN_ + nk) * 768 + head * 32 + c;
            } else {
                base = (size_t)(bt * HWP_ + kk) * 768 + head * 32 + c;
            }
            cpa16(Kd + j * KP + c, qkv + base + 256);
            cpa16(Vd + j * VP + c, qkv + base + 512);
        }
    };

    for (int f = tid; f < 1024; f += 256) {
        int r = f >> 3, c = (f & 7) << 2;
        int rq = min(q0 + r, Lq - 1);
        const __half2* src;
        if (TMP) {
            int nq = (rq / 28) * HWP_ + fixed * fs + (rq % 28) * vs;
            src = qsrc + (size_t)(b * NN_ + nq) * qstride + head * 32 + c;
        } else {
            src = qsrc + (size_t)(bt * HWP_ + rq) * qstride + head * 32 + c;
        }
        cpa16(Qs + r * QP + c, src);
    }
    stageKV(0, 0);
    CP_COMMIT();

    const int r0 = q0 + warp * 16 + row;
    const int lim0 = TMP ? min((r0 / 28 + 1) * 28, 112) : HWP_;
    const int lim1 = TMP ? min(((r0 + 8) / 28 + 1) * 28, 112) : HWP_;
    const int warpLim = TMP ? min(((q0 + warp * 16 + 15) / 28 + 1) * 28, 112) : HWP_;

    unsigned q[4][4];
    float m0 = -1e30f, m1 = -1e30f, l0 = 0.f, l1 = 0.f;
    float4 o[8];
#pragma unroll
    for (int nt = 0; nt < 8; nt++) o[nt] = make_float4(0.f, 0.f, 0.f, 0.f);

    unsigned* Ps = Qs + warp * 16 * QP;
    const unsigned kfrag_off = (unsigned)(lane & 15) * 144u + (unsigned)(lane >> 4) * 16u;

    for (int kt = 0, cur = 0; kt < kmaxb; kt += 64, cur ^= 1) {
        if (kt + 64 < kmaxb) stageKV(cur ^ 1, kt + 64);
        CP_COMMIT();
        CP_WAIT(1);
        __syncthreads();

        unsigned* Ks = Kb + cur * KTILE;
        unsigned* Vs = Vb + cur * VTILE;

        if (kt == 0) {   // Q resident; canonical a-frags, before Qs becomes P
            int rm = warp * 16 + row;
#pragma unroll
            for (int kd = 0; kd < 4; kd++) {
                q[kd][0] = Qs[rm * QP + kd * 8 + t4];
                q[kd][1] = Qs[(rm + 8) * QP + kd * 8 + t4];
                q[kd][2] = Qs[rm * QP + kd * 8 + 4 + t4];
                q[kd][3] = Qs[(rm + 8) * QP + kd * 8 + 4 + t4];
            }
        }

        if (kt < warpLim) {
            // ---- S = Q @ K^T via ldmatrix.x4 K fragments ----
            unsigned kfb = (unsigned)__cvta_generic_to_shared(Ks) + kfrag_off;
            float4 s[8];
#pragma unroll
            for (int nt = 0; nt < 8; nt++) s[nt] = make_float4(0.f, 0.f, 0.f, 0.f);
#pragma unroll
            for (int g = 0; g < 4; g++) {
#pragma unroll
                for (int kd = 0; kd < 4; kd++) {
                    unsigned r0v, r1v, r2v, r3v;
                    ldmx4(r0v, r1v, r2v, r3v, kfb + g * 2304 + kd * 32);
                    mma16(s[2*g],   q[kd], r0v, r2v);
                    mma16(s[2*g+1], q[kd], r1v, r3v);
                }
            }

            if (TMP || kt + 64 > HWP_) {
                int cb = kt + 2 * t4;
#pragma unroll
                for (int nt = 0; nt < 8; nt++) {
                    int c0 = cb + 8 * nt;
                    if (c0     >= lim0) s[nt].x = -1e30f;
                    if (c0 + 1 >= lim0) s[nt].y = -1e30f;
                    if (c0     >= lim1) s[nt].z = -1e30f;
                    if (c0 + 1 >= lim1) s[nt].w = -1e30f;
                }
            }
            float mx0 = -1e30f, mx1 = -1e30f;
#pragma unroll
            for (int nt = 0; nt < 8; nt++) {
                mx0 = fmaxf(mx0, fmaxf(s[nt].x, s[nt].y));
                mx1 = fmaxf(mx1, fmaxf(s[nt].z, s[nt].w));
            }
            mx0 = fmaxf(mx0, __shfl_xor_sync(0xffffffffu, mx0, 1));
            mx0 = fmaxf(mx0, __shfl_xor_sync(0xffffffffu, mx0, 2));
            mx1 = fmaxf(mx1, __shfl_xor_sync(0xffffffffu, mx1, 1));
            mx1 = fmaxf(mx1, __shfl_xor_sync(0xffffffffu, mx1, 2));
            float mn0 = fmaxf(m0, mx0), mn1 = fmaxf(m1, mx1);
            float corr0 = __expf(m0 - mn0), corr1 = __expf(m1 - mn1);
            float ps0 = 0.f, ps1 = 0.f;
#pragma unroll
            for (int nt = 0; nt < 8; nt++) {
                s[nt].x = __expf(s[nt].x - mn0); ps0 += s[nt].x;
                s[nt].y = __expf(s[nt].y - mn0); ps0 += s[nt].y;
                s[nt].z = __expf(s[nt].z - mn1); ps1 += s[nt].z;
                s[nt].w = __expf(s[nt].w - mn1); ps1 += s[nt].w;
            }
            ps0 += __shfl_xor_sync(0xffffffffu, ps0, 1);
            ps0 += __shfl_xor_sync(0xffffffffu, ps0, 2);
            ps1 += __shfl_xor_sync(0xffffffffu, ps1, 1);
            ps1 += __shfl_xor_sync(0xffffffffu, ps1, 2);
            l0 = l0 * corr0 + ps0; l1 = l1 * corr1 + ps1;
            m0 = mn0; m1 = mn1;
#pragma unroll
            for (int nt = 0; nt < 8; nt++) {
                o[nt].x *= corr0; o[nt].y *= corr0;
                o[nt].z *= corr1; o[nt].w *= corr1;
            }

            // ---- store P (fp16 pairs, sigma positions; warp-private) ----
#pragma unroll
            for (int nt = 0; nt < 8; nt++) {
                int pos = 8 * (nt >> 1) + 2 * t4 + (nt & 1);
                Ps[row * QP + pos]       = h2u(s[nt].x, s[nt].y);
                Ps[(row + 8) * QP + pos] = h2u(s[nt].z, s[nt].w);
            }
            __syncwarp();

            // ---- O += P @ V (V via ldmatrix.x2.trans) ----
            unsigned vsb = (unsigned)__cvta_generic_to_shared(Vs);
#pragma unroll
            for (int kk = 0; kk < 4; kk++) {
                uint2 u0 = *(const uint2*)(Ps + row * QP + kk * 8 + 2 * t4);
                uint2 u1 = *(const uint2*)(Ps + (row + 8) * QP + kk * 8 + 2 * t4);
                unsigned a[4] = {u0.x, u1.x, u0.y, u1.y};
                unsigned rowaddr = vsb + (unsigned)((kk * 16 + (lane & 15)) * VP) * 4u;
#pragma unroll
                for (int nt = 0; nt < 8; nt++) {
                    unsigned b0, b1;
                    ldmx2t(b0, b1, rowaddr + nt * 16);
                    mma16(o[nt], a, b0, b1);
                }
            }
            __syncwarp();
        }
        __syncthreads();
    }

    // ---- epilogue: normalize, fp16-round to sigma-paired layout ----
    float inv0 = 1.f / l0, inv1 = 1.f / l1;
#pragma unroll
    for (int nt = 0; nt < 8; nt++) {
        int pos = 8 * (nt >> 1) + 2 * t4 + (nt & 1);
        if (r0 < Lq) {
            size_t ob;
            if (TMP) {
                int nq = (r0 / 28) * HWP_ + fixed * fs + (r0 % 28) * vs;
                ob = (size_t)(b * NN_ + nq) * 256 + head * 32 + pos;
            } else {
                ob = (size_t)(bt * HWP_ + r0) * 256 + head * 32 + pos;
            }
            float rx = o[nt].x * inv0, ry = o[nt].y * inv0;
            if (TMP && accum) {
                __half2 old = out[ob];
                rx += __low2float(old); ry += __high2float(old);
            }
            out[ob] = __floats2half2_rn(rx, ry);
        }
        if (r0 + 8 < Lq) {
            int r1 = r0 + 8;
            size_t ob;
            if (TMP) {
                int nq = (r1 / 28) * HWP_ + fixed * fs + (r1 % 28) * vs;
                ob = (size_t)(b * NN_ + nq) * 256 + head * 32 + pos;
            } else {
                ob = (size_t)(bt * HWP_ + r1) * 256 + head * 32 + pos;
            }
            float rx = o[nt].z * inv1, ry = o[nt].w * inv1;
            if (TMP && accum) {
                __half2 old = out[ob];
                rx += __low2float(old); ry += __high2float(old);
            }
            out[ob] = __floats2half2_rn(rx, ry);
        }
    }
}

// ---------------------------------------------------------------------------
extern "C" void kernel_launch(void* const* d_in, const int* in_sizes, int n_in,
                              void* d_out, int out_size)
{
    const float* x      = (const float*)d_in[0];
    const float* w_in   = (const float*)d_in[1];
    const float* b_in   = (const float*)d_in[2];
    const float* w_out  = (const float*)d_in[3];
    const float* b_out  = (const float*)d_in[4];
    const float* w_t    = (const float*)d_in[5];
    const float* b_t    = (const float*)d_in[6];
    const float* w_to   = (const float*)d_in[7];
    const float* b_to   = (const float*)d_in[8];
    const float* alpha  = (const float*)d_in[9];
    float* out = (float*)d_out;

    __half2 *qkv, *sp, *qt, *ot, *gx, *gw1, *gw2, *gw3;
    cudaGetSymbolAddress((void**)&qkv, g_qkv);
    cudaGetSymbolAddress((void**)&sp,  g_sp);
    cudaGetSymbolAddress((void**)&qt,  g_qt);
    cudaGetSymbolAddress((void**)&ot,  g_ot);
    cudaGetSymbolAddress((void**)&gx,  g_x);
    cudaGetSymbolAddress((void**)&gw1, g_w1);
    cudaGetSymbolAddress((void**)&gw2, g_w2);
    cudaGetSymbolAddress((void**)&gw3, g_w3);

    cudaFuncSetAttribute(gemm_h,     cudaFuncAttributeMaxDynamicSharedMemorySize, GSMEM);
    cudaFuncSetAttribute(flash_h<0>, cudaFuncAttributeMaxDynamicSharedMemorySize, FSMEM);
    cudaFuncSetAttribute(flash_h<1>, cudaFuncAttributeMaxDynamicSharedMemorySize, FSMEM);

    // 0) fp16-round + sigma-permute x + weights
    prep_h<<<NPG / 256, 256>>>(
        (const float4*)x, (const float4*)w_in, (const float4*)w_t,
        (const float4*)w_out, (const float4*)w_to,
        (uint4*)gx, (uint4*)gw1, (uint4*)gw2, (uint4*)gw3);

    // 1) merged qkv + qt projection (N=2048)
    gemm_h<<<dim3(16, 98), 256, GSMEM>>>(
        (const __half*)gx, (const __half*)gw1, b_in, b_t,
        nullptr, qkv, qt, nullptr, 2048, 3);

    // 2) spatial attention -> sp
    flash_h<0><<<dim3(7, NH_, 16), 256, FSMEM>>>(qkv, qkv, 768, sp, 0, 0, 0);

    // 3) xs = sp @ w_out^T + b_out -> out (f32)
    gemm_h<<<dim3(4, 98), 256, GSMEM>>>(
        (const __half*)sp, (const __half*)gw2, b_out, nullptr,
        out, nullptr, nullptr, nullptr, 512, 0);

    // 4) temporal-H: ot = o_th
    flash_h<1><<<dim3(1, NH_, B_ * 28), 256, FSMEM>>>(qkv, qt, 256, ot, 1, 28, 0);

    // 5) temporal-W: ot += o_tw
    flash_h<1><<<dim3(1, NH_, B_ * 28), 256, FSMEM>>>(qkv, qt, 256, ot, 28, 1, 1);

    // 6) out = xs + alpha * (ot @ w_to^T + b_to)
    gemm_h<<<dim3(4, 98), 256, GSMEM>>>(
        (const __half*)ot, (const __half*)gw3, b_to, nullptr,
        out, nullptr, nullptr, alpha, 512, 2);
}

// round 10
// speedup vs baseline: 2.6839x; 1.0754x over previous
#include <cuda_runtime.h>
#include <cuda_fp16.h>
#include <math.h>

#define B_    4
#define E_    512
#define NH_   8
#define HWP_  784
#define NN_   3136
#define ROWS_ 12544
#define QS2_  0.1803368801111f   // 0.125 * log2(e): S comes out in log2 domain
#define CEXP_ 4.0f               // static softmax shift (log2 domain)

// fp16 scratch. q/k of qkv, qt, sp, ot: sigma-permuted half2 pairs per 8-pair
// group (stored pos sigma(p)=2(p&3)+(p>>2)); v part of qkv: natural (ldmatrix).
__device__ __half2 g_qkv[ROWS_ * 768];
__device__ __half2 g_sp [ROWS_ * 256];
__device__ __half2 g_qt [ROWS_ * 256];
__device__ __half2 g_ot [ROWS_ * 256];
__device__ __half2 g_x  [ROWS_ * 256];
__device__ __half2 g_w1 [2048 * 256];
__device__ __half2 g_w2 [512 * 256];   // w_out
__device__ __half2 g_w3 [512 * 256];   // alpha (.) w_to

__device__ __forceinline__ unsigned h2u(float a, float b) {
    __half2 h = __floats2half2_rn(a, b);
    return *(unsigned*)&h;
}
__device__ __forceinline__ float ex2f(float x) {
    float r; asm("ex2.approx.f32 %0, %1;" : "=f"(r) : "f"(x)); return r;
}
__device__ __forceinline__ void mma16(float4& d, const unsigned* a, unsigned b0, unsigned b1) {
    asm volatile("mma.sync.aligned.m16n8k16.row.col.f32.f16.f16.f32 "
        "{%0,%1,%2,%3},{%4,%5,%6,%7},{%8,%9},{%0,%1,%2,%3};"
        : "+f"(d.x), "+f"(d.y), "+f"(d.z), "+f"(d.w)
        : "r"(a[0]), "r"(a[1]), "r"(a[2]), "r"(a[3]), "r"(b0), "r"(b1));
}
__device__ __forceinline__ void ldmx4(unsigned& r0, unsigned& r1, unsigned& r2,
                                      unsigned& r3, unsigned addr) {
    asm volatile("ldmatrix.sync.aligned.m8n8.x4.shared.b16 {%0,%1,%2,%3}, [%4];"
        : "=r"(r0), "=r"(r1), "=r"(r2), "=r"(r3) : "r"(addr));
}
__device__ __forceinline__ void ldmx2t(unsigned& b0, unsigned& b1, unsigned addr) {
    asm volatile("ldmatrix.sync.aligned.m8n8.x2.trans.shared.b16 {%0,%1}, [%2];"
        : "=r"(b0), "=r"(b1) : "r"(addr));
}
__device__ __forceinline__ void cpa16(void* sdst, const void* gsrc) {
    unsigned s = (unsigned)__cvta_generic_to_shared(sdst);
    asm volatile("cp.async.ca.shared.global [%0], [%1], 16;" :: "r"(s), "l"(gsrc));
}
__device__ __forceinline__ void cpa16s(unsigned sdst, const void* gsrc) {
    asm volatile("cp.async.ca.shared.global [%0], [%1], 16;" :: "r"(sdst), "l"(gsrc));
}
#define CP_COMMIT() asm volatile("cp.async.commit_group;" ::: "memory")
#define CP_WAIT(n)  asm volatile("cp.async.wait_group %0;" :: "n"(n) : "memory")

// ---------------------------------------------------------------------------
// Prep: fp16-round + sigma-permute. w_to rows additionally scaled by alpha[n].
// ---------------------------------------------------------------------------
#define NXG  401408
#define NWIG 49152
#define NWG  16384
#define NPG  (NXG + NWIG + 4 * NWG)

__global__ __launch_bounds__(256)
void prep_h(const float4* __restrict__ x,  const float4* __restrict__ w_in,
            const float4* __restrict__ w_t, const float4* __restrict__ w_out,
            const float4* __restrict__ w_to, const float* __restrict__ alpha,
            uint4* __restrict__ gx, uint4* __restrict__ gw1,
            uint4* __restrict__ gw2, uint4* __restrict__ gw3)
{
    long i = (long)blockIdx.x * 256 + threadIdx.x;
    const float4* s; uint4* d;
    float am = 1.f;
    if      (i < NXG)                 { s = x + 4*i;                        d = gx + 2*i; }
    else if (i < NXG + NWIG)          { long j = i - NXG;                   s = w_in + 4*j;  d = gw1 + 2*j; }
    else if (i < NXG + NWIG + NWG)    { long j = i - NXG - NWIG;            s = w_t + 4*j;   d = gw1 + 2*(NWIG + j); }
    else if (i < NXG + NWIG + 2*NWG)  { long j = i - NXG - NWIG - NWG;      s = w_out + 4*j; d = gw2 + 2*j; }
    else if (i < NPG)                 { long j = i - NXG - NWIG - 2*NWG;    s = w_to + 4*j;  d = gw3 + 2*j;
                                        am = alpha[(int)(j >> 5)]; }
    else return;
    float4 f0 = s[0], f1 = s[1], f2 = s[2], f3 = s[3];
    f0.x *= am; f0.y *= am; f0.z *= am; f0.w *= am;
    f1.x *= am; f1.y *= am; f1.z *= am; f1.w *= am;
    f2.x *= am; f2.y *= am; f2.z *= am; f2.w *= am;
    f3.x *= am; f3.y *= am; f3.z *= am; f3.w *= am;
    unsigned h0 = h2u(f0.x, f0.y), h1 = h2u(f0.z, f0.w);
    unsigned h2 = h2u(f1.x, f1.y), h3 = h2u(f1.z, f1.w);
    unsigned h4 = h2u(f2.x, f2.y), h5 = h2u(f2.z, f2.w);
    unsigned h6 = h2u(f3.x, f3.y), h7 = h2u(f3.z, f3.w);
    d[0] = make_uint4(h0, h4, h1, h5);
    d[1] = make_uint4(h2, h6, h3, h7);
}

// ---------------------------------------------------------------------------
// fp16 GEMM via mma.sync + ldmatrix.x4. 4-stage cp.async, BK=32 halfs,
// smem row pitch 80 B. Per-slab A/W source selected by k0 (<512 -> A0/W0,
// else A1/W1 at k0&511) so two K=512 products fuse into one K=1024 pass.
// mode 3: merged qkv+qt: col<512 q(*QS2_,sigma) | <1024 k(sigma) |
//         <1536 v(natural) -> Ch ; >=1536 qt(*QS2_,sigma) -> C2
// mode 4: Cf = acc + bias[n] + alpha[n]*bias2[n]   (fused output GEMM)
// ---------------------------------------------------------------------------
#define STGB  10240u
#define GSMEM (8 * 10240)

__global__ __launch_bounds__(256, 2)
void gemm_h(const __half* __restrict__ A0, const __half* __restrict__ A1,
            const __half* __restrict__ W0, const __half* __restrict__ W1,
            const float* __restrict__ bias, const float* __restrict__ bias2,
            float* __restrict__ Cf, __half2* __restrict__ Ch, __half2* __restrict__ C2,
            const float* __restrict__ alpha, int N, int K, int mode)
{
    extern __shared__ __half gsmh[];
    const unsigned sbase = (unsigned)__cvta_generic_to_shared(gsmh);
    const int bm = blockIdx.y * 128, bn = blockIdx.x * 128;
    const int tid  = threadIdx.x;
    const int warp = tid >> 5, lane = tid & 31;
    const int wm = (warp >> 1) * 32, wn = (warp & 1) * 64;
    const int row = lane >> 2, t4 = lane & 3;

    const int srow  = tid >> 1;
    const int sslot = (tid & 1) * 2;
    const unsigned soff = (unsigned)srow * 80u + (unsigned)sslot * 16u;
    const size_t arow = (size_t)(bm + srow) * 512 + sslot * 8;
    const size_t wrow = (size_t)(bn + srow) * 512 + sslot * 8;

    auto stage = [&](int s, int k0) {
        const __half* Ab = ((k0 < 512) ? A0 : A1) + arow + (k0 & 511);
        const __half* Wb = ((k0 < 512) ? W0 : W1) + wrow + (k0 & 511);
        unsigned d = sbase + (unsigned)s * STGB + soff;
        cpa16s(d,      Ab);
        cpa16s(d + 16, Ab + 8);
        unsigned d2 = d + 4 * STGB;
        cpa16s(d2,      Wb);
        cpa16s(d2 + 16, Wb + 8);
    };

    const unsigned aoff = (unsigned)(wm + (lane & 15)) * 80u + (unsigned)(lane >> 4) * 16u;
    const unsigned boff = 4 * STGB + (unsigned)(wn + (lane & 15)) * 80u + (unsigned)(lane >> 4) * 16u;

    float4 acc[2][8];
#pragma unroll
    for (int i = 0; i < 2; i++)
#pragma unroll
        for (int j = 0; j < 8; j++) acc[i][j] = make_float4(0.f, 0.f, 0.f, 0.f);

    const int nsl = K >> 5;
    stage(0, 0);  CP_COMMIT();
    stage(1, 32); CP_COMMIT();

    for (int i = 0; i < nsl; i++) {
        if (i + 2 < nsl) stage((i + 2) & 3, (i + 2) * 32);
        CP_COMMIT();
        CP_WAIT(2);
        __syncthreads();

        unsigned ab = sbase + (unsigned)(i & 3) * STGB + aoff;
        unsigned bb = sbase + (unsigned)(i & 3) * STGB + boff;
#pragma unroll
        for (int ks = 0; ks < 2; ks++) {
            unsigned a[2][4];
            ldmx4(a[0][0], a[0][1], a[0][2], a[0][3], ab + ks * 32);
            ldmx4(a[1][0], a[1][1], a[1][2], a[1][3], ab + 1280 + ks * 32);
#pragma unroll
            for (int g = 0; g < 4; g++) {
                unsigned r0, r1, r2, r3;
                ldmx4(r0, r1, r2, r3, bb + g * 1280 + ks * 32);
                mma16(acc[0][2*g],   a[0], r0, r2);
                mma16(acc[0][2*g+1], a[0], r1, r3);
                mma16(acc[1][2*g],   a[1], r0, r2);
                mma16(acc[1][2*g+1], a[1], r1, r3);
            }
        }
    }

#pragma unroll
    for (int mt = 0; mt < 2; mt++) {
        int rg = bm + wm + mt * 16 + row;
#pragma unroll
        for (int nt = 0; nt < 8; nt++) {
            int cg = bn + wn + nt * 8 + 2 * t4;
            float v0 = acc[mt][nt].x, v1 = acc[mt][nt].y;
            float v2 = acc[mt][nt].z, v3 = acc[mt][nt].w;
            if (mode == 3) {
                float bb0, bb1, sc;
                __half2* dst; int off, dstr; bool natural;
                if (cg < 1536) {
                    bb0 = bias[cg]; bb1 = bias[cg + 1];
                    sc = (cg < 512) ? QS2_ : 1.f;
                    dst = Ch; off = 0; dstr = 768; natural = (cg >= 1024);
                } else {
                    bb0 = bias2[cg - 1536]; bb1 = bias2[cg - 1535];
                    sc = QS2_;
                    dst = C2; off = 1536; dstr = 256; natural = false;
                }
                v0 = (v0 + bb0) * sc; v1 = (v1 + bb1) * sc;
                v2 = (v2 + bb0) * sc; v3 = (v3 + bb1) * sc;
                int pd = (cg - off) >> 1;
                int pos = natural ? pd : ((pd & ~7) + 2 * (pd & 3) + ((pd >> 2) & 1));
                dst[(size_t)rg * dstr + pos]       = __floats2half2_rn(v0, v1);
                dst[(size_t)(rg + 8) * dstr + pos] = __floats2half2_rn(v2, v3);
            } else {   // mode 4: fused output epilogue
                float bb0 = bias[cg] + alpha[cg] * bias2[cg];
                float bb1 = bias[cg + 1] + alpha[cg + 1] * bias2[cg + 1];
                v0 += bb0; v1 += bb1; v2 += bb0; v3 += bb1;
                size_t i0 = (size_t)rg * N + cg;
                size_t i1 = (size_t)(rg + 8) * N + cg;
                *(float2*)(Cf + i0) = make_float2(v0, v1);
                *(float2*)(Cf + i1) = make_float2(v2, v3);
            }
        }
    }
}

// ---------------------------------------------------------------------------
// fp16 flash attention, static-shift exp2 softmax (no online max).
// 256 thr = 8 warps, BQ=128, key tiles 64, D=64. Q canonical frags; K via
// ldmatrix.x4 (pitch 144 B); V natural via ldmatrix.x2.trans; P sigma-paired.
// Runtime dispatch: blockIdx.z >= zsplit -> temporal axial (L=112, causal
// prefix), else spatial frame (L=784). p = ex2(s - CEXP_); l reduced once.
// ---------------------------------------------------------------------------
#define QP 40
#define KP 36
#define VP 36
#define KTILE (64 * KP)
#define VTILE (64 * VP)
#define FSMEM ((128 * QP + 2 * KTILE + 2 * VTILE) * 4)

__global__ __launch_bounds__(256, 2)
void flash_h(const __half2* __restrict__ qkv, const __half2* __restrict__ qt,
             __half2* __restrict__ outsp, __half2* __restrict__ outt,
             int zsplit, int fs, int vs, int accum)
{
    const int z = blockIdx.z;
    const bool tmp = (z >= zsplit);
    if (tmp && blockIdx.x != 0) return;

    extern __shared__ unsigned sm[];
    unsigned* Qs = sm;
    unsigned* Kb = sm + 128 * QP;
    unsigned* Vb = Kb + 2 * KTILE;

    const int tid  = threadIdx.x;
    const int warp = tid >> 5, lane = tid & 31;
    const int row  = lane >> 2, t4 = lane & 3;
    const int head = blockIdx.y;
    const int q0   = blockIdx.x * 128;

    int b = 0, fixed = 0, bt = 0;
    if (tmp) { int bz = z - zsplit; b = bz / 28; fixed = bz % 28; }
    else     { bt = z; }

    const __half2* qsrc = tmp ? qt : qkv;
    const int qstride   = tmp ? 256 : 768;
    __half2* out        = tmp ? outt : outsp;

    const int Lq    = tmp ? 112 : HWP_;
    const int lastr = min(q0 + 127, Lq - 1);
    const int kmaxb = tmp ? (lastr / 28 + 1) * 28 : HWP_;

    auto stageKV = [&](int buf, int ktt) {
        unsigned* Kd = Kb + buf * KTILE;
        unsigned* Vd = Vb + buf * VTILE;
        for (int f = tid; f < 512; f += 256) {
            int j = f >> 3, c = (f & 7) << 2;
            int kk = min(ktt + j, kmaxb - 1);
            size_t base;
            if (tmp) {
                int nk = (kk / 28) * HWP_ + fixed * fs + (kk % 28) * vs;
                base = (size_t)(b * NN_ + nk) * 768 + head * 32 + c;
            } else {
                base = (size_t)(bt * HWP_ + kk) * 768 + head * 32 + c;
            }
            cpa16(Kd + j * KP + c, qkv + base + 256);
            cpa16(Vd + j * VP + c, qkv + base + 512);
        }
    };

    for (int f = tid; f < 1024; f += 256) {
        int r = f >> 3, c = (f & 7) << 2;
        int rq = min(q0 + r, Lq - 1);
        const __half2* src;
        if (tmp) {
            int nq = (rq / 28) * HWP_ + fixed * fs + (rq % 28) * vs;
            src = qsrc + (size_t)(b * NN_ + nq) * qstride + head * 32 + c;
        } else {
            src = qsrc + (size_t)(bt * HWP_ + rq) * qstride + head * 32 + c;
        }
        cpa16(Qs + r * QP + c, src);
    }
    stageKV(0, 0);
    CP_COMMIT();

    const int r0 = q0 + warp * 16 + row;
    const int lim0 = tmp ? min((r0 / 28 + 1) * 28, 112) : HWP_;
    const int lim1 = tmp ? min(((r0 + 8) / 28 + 1) * 28, 112) : HWP_;
    const int warpLim = tmp ? min(((q0 + warp * 16 + 15) / 28 + 1) * 28, 112) : HWP_;

    unsigned q[4][4];
    float l0 = 0.f, l1 = 0.f;
    float4 o[8];
#pragma unroll
    for (int nt = 0; nt < 8; nt++) o[nt] = make_float4(0.f, 0.f, 0.f, 0.f);

    unsigned* Ps = Qs + warp * 16 * QP;
    const unsigned kfrag_off = (unsigned)(lane & 15) * 144u + (unsigned)(lane >> 4) * 16u;

    for (int kt = 0, cur = 0; kt < kmaxb; kt += 64, cur ^= 1) {
        if (kt + 64 < kmaxb) stageKV(cur ^ 1, kt + 64);
        CP_COMMIT();
        CP_WAIT(1);
        __syncthreads();

        unsigned* Ks = Kb + cur * KTILE;
        unsigned* Vs = Vb + cur * VTILE;

        if (kt == 0) {   // Q resident; canonical a-frags, before Qs becomes P
            int rm = warp * 16 + row;
#pragma unroll
            for (int kd = 0; kd < 4; kd++) {
                q[kd][0] = Qs[rm * QP + kd * 8 + t4];
                q[kd][1] = Qs[(rm + 8) * QP + kd * 8 + t4];
                q[kd][2] = Qs[rm * QP + kd * 8 + 4 + t4];
                q[kd][3] = Qs[(rm + 8) * QP + kd * 8 + 4 + t4];
            }
        }

        if (kt < warpLim) {
            // ---- S = Q @ K^T (log2 domain) ----
            unsigned kfb = (unsigned)__cvta_generic_to_shared(Ks) + kfrag_off;
            float4 s[8];
#pragma unroll
            for (int nt = 0; nt < 8; nt++) s[nt] = make_float4(0.f, 0.f, 0.f, 0.f);
#pragma unroll
            for (int g = 0; g < 4; g++) {
#pragma unroll
                for (int kd = 0; kd < 4; kd++) {
                    unsigned r0v, r1v, r2v, r3v;
                    ldmx4(r0v, r1v, r2v, r3v, kfb + g * 2304 + kd * 32);
                    mma16(s[2*g],   q[kd], r0v, r2v);
                    mma16(s[2*g+1], q[kd], r1v, r3v);
                }
            }

            if (tmp || kt + 64 > HWP_) {
                int cb = kt + 2 * t4;
#pragma unroll
                for (int nt = 0; nt < 8; nt++) {
                    int c0 = cb + 8 * nt;
                    if (c0     >= lim0) s[nt].x = -1e30f;
                    if (c0 + 1 >= lim0) s[nt].y = -1e30f;
                    if (c0     >= lim1) s[nt].z = -1e30f;
                    if (c0 + 1 >= lim1) s[nt].w = -1e30f;
                }
            }

            // ---- static-shift softmax numerator ----
#pragma unroll
            for (int nt = 0; nt < 8; nt++) {
                s[nt].x = ex2f(s[nt].x - CEXP_); l0 += s[nt].x;
                s[nt].y = ex2f(s[nt].y - CEXP_); l0 += s[nt].y;
                s[nt].z = ex2f(s[nt].z - CEXP_); l1 += s[nt].z;
                s[nt].w = ex2f(s[nt].w - CEXP_); l1 += s[nt].w;
            }

            // ---- store P (fp16 pairs, sigma positions; warp-private) ----
#pragma unroll
            for (int nt = 0; nt < 8; nt++) {
                int pos = 8 * (nt >> 1) + 2 * t4 + (nt & 1);
                Ps[row * QP + pos]       = h2u(s[nt].x, s[nt].y);
                Ps[(row + 8) * QP + pos] = h2u(s[nt].z, s[nt].w);
            }
            __syncwarp();

            // ---- O += P @ V (V via ldmatrix.x2.trans) ----
            unsigned vsb = (unsigned)__cvta_generic_to_shared(Vs);
#pragma unroll
            for (int kk = 0; kk < 4; kk++) {
                uint2 u0 = *(const uint2*)(Ps + row * QP + kk * 8 + 2 * t4);
                uint2 u1 = *(const uint2*)(Ps + (row + 8) * QP + kk * 8 + 2 * t4);
                unsigned a[4] = {u0.x, u1.x, u0.y, u1.y};
                unsigned rowaddr = vsb + (unsigned)((kk * 16 + (lane & 15)) * VP) * 4u;
#pragma unroll
                for (int nt = 0; nt < 8; nt++) {
                    unsigned b0, b1;
                    ldmx2t(b0, b1, rowaddr + nt * 16);
                    mma16(o[nt], a, b0, b1);
                }
            }
            __syncwarp();
        }
        __syncthreads();
    }

    // ---- single end-of-kernel l reduction, normalize, store ----
    l0 += __shfl_xor_sync(0xffffffffu, l0, 1);
    l0 += __shfl_xor_sync(0xffffffffu, l0, 2);
    l1 += __shfl_xor_sync(0xffffffffu, l1, 1);
    l1 += __shfl_xor_sync(0xffffffffu, l1, 2);
    float inv0 = 1.f / l0, inv1 = 1.f / l1;
#pragma unroll
    for (int nt = 0; nt < 8; nt++) {
        int pos = 8 * (nt >> 1) + 2 * t4 + (nt & 1);
        if (r0 < Lq) {
            size_t ob;
            if (tmp) {
                int nq = (r0 / 28) * HWP_ + fixed * fs + (r0 % 28) * vs;
                ob = (size_t)(b * NN_ + nq) * 256 + head * 32 + pos;
            } else {
                ob = (size_t)(bt * HWP_ + r0) * 256 + head * 32 + pos;
            }
            float rx = o[nt].x * inv0, ry = o[nt].y * inv0;
            if (tmp && accum) {
                __half2 old = out[ob];
                rx += __low2float(old); ry += __high2float(old);
            }
            out[ob] = __floats2half2_rn(rx, ry);
        }
        if (r0 + 8 < Lq) {
            int r1 = r0 + 8;
            size_t ob;
            if (tmp) {
                int nq = (r1 / 28) * HWP_ + fixed * fs + (r1 % 28) * vs;
                ob = (size_t)(b * NN_ + nq) * 256 + head * 32 + pos;
            } else {
                ob = (size_t)(bt * HWP_ + r1) * 256 + head * 32 + pos;
            }
            float rx = o[nt].z * inv1, ry = o[nt].w * inv1;
            if (tmp && accum) {
                __half2 old = out[ob];
                rx += __low2float(old); ry += __high2float(old);
            }
            out[ob] = __floats2half2_rn(rx, ry);
        }
    }
}

// ---------------------------------------------------------------------------
extern "C" void kernel_launch(void* const* d_in, const int* in_sizes, int n_in,
                              void* d_out, int out_size)
{
    const float* x      = (const float*)d_in[0];
    const float* w_in   = (const float*)d_in[1];
    const float* b_in   = (const float*)d_in[2];
    const float* w_out  = (const float*)d_in[3];
    const float* b_out  = (const float*)d_in[4];
    const float* w_t    = (const float*)d_in[5];
    const float* b_t    = (const float*)d_in[6];
    const float* w_to   = (const float*)d_in[7];
    const float* b_to   = (const float*)d_in[8];
    const float* alpha  = (const float*)d_in[9];
    float* out = (float*)d_out;

    __half2 *qkv, *sp, *qt, *ot, *gx, *gw1, *gw2, *gw3;
    cudaGetSymbolAddress((void**)&qkv, g_qkv);
    cudaGetSymbolAddress((void**)&sp,  g_sp);
    cudaGetSymbolAddress((void**)&qt,  g_qt);
    cudaGetSymbolAddress((void**)&ot,  g_ot);
    cudaGetSymbolAddress((void**)&gx,  g_x);
    cudaGetSymbolAddress((void**)&gw1, g_w1);
    cudaGetSymbolAddress((void**)&gw2, g_w2);
    cudaGetSymbolAddress((void**)&gw3, g_w3);

    cudaFuncSetAttribute(gemm_h,  cudaFuncAttributeMaxDynamicSharedMemorySize, GSMEM);
    cudaFuncSetAttribute(flash_h, cudaFuncAttributeMaxDynamicSharedMemorySize, FSMEM);

    // 0) fp16-round + sigma-permute x + weights; w_to pre-scaled by alpha
    prep_h<<<NPG / 256, 256>>>(
        (const float4*)x, (const float4*)w_in, (const float4*)w_t,
        (const float4*)w_out, (const float4*)w_to, alpha,
        (uint4*)gx, (uint4*)gw1, (uint4*)gw2, (uint4*)gw3);

    // 1) merged qkv + qt projection (N=2048, K=512)
    gemm_h<<<dim3(16, 98), 256, GSMEM>>>(
        (const __half*)gx, (const __half*)gx,
        (const __half*)gw1, (const __half*)gw1,
        b_in, b_t, nullptr, qkv, qt, nullptr, 2048, 512, 3);

    // 2) spatial attention (z<16) + temporal-H (z>=16) in one launch
    flash_h<<<dim3(7, NH_, 16 + B_ * 28), 256, FSMEM>>>(
        qkv, qt, sp, ot, /*zsplit=*/16, /*fs=*/1, /*vs=*/28, /*accum=*/0);

    // 3) temporal-W: ot += o_tw
    flash_h<<<dim3(1, NH_, B_ * 28), 256, FSMEM>>>(
        qkv, qt, sp, ot, /*zsplit=*/0, /*fs=*/28, /*vs=*/1, /*accum=*/1);

    // 4) fused output: out = sp@w_out^T + ot@(alpha.w_to)^T + b_out + alpha.b_to
    gemm_h<<<dim3(4, 98), 256, GSMEM>>>(
        (const __half*)sp, (const __half*)ot,
        (const __half*)gw2, (const __half*)gw3,
        b_out, b_to, out, nullptr, nullptr, alpha, 512, 1024, 4);
}